// round 6
// baseline (speedup 1.0000x reference)
#include <cuda_runtime.h>
#include <math.h>
#include <stdint.h>

// ---------------------------------------------------------------------------
// Problem constants
// ---------------------------------------------------------------------------
#define Bn    64
#define Tn    512
#define HIDn  512
#define Hn    256
#define G4n   1024           // 4*H
#define NLn   9
#define BTn   (Bn*Tn)        // 32768
#define NBLK  128            // persistent LSTM CTAs (<=148 SMs -> co-resident)
#define WS    260            // padded smem row stride (floats): 16B aligned, 4-bank skew
#define LSTM_SMEM ((80*WS + 64*17) * 4)   // w_s(64 rows)+h_s(16 rows)+g_s = 87552 B

// ---------------------------------------------------------------------------
// Device scratch (cudaMalloc forbidden -> module globals)
// ---------------------------------------------------------------------------
__device__ float g_xA[BTn*HIDn];          // 64 MB
__device__ float g_xB[BTn*HIDn];          // 64 MB
__device__ float g_xp[2ll*BTn*G4n];       // 256 MB  [dir][bt][gate-row]
__device__ float g_h[2*2*Bn*Hn];          // [phase][dir][b][u] double-buffered h
__device__ float g_logits[BTn*NLn];
__device__ float g_crf[Bn];
__device__ unsigned int g_bar[2];

// ---------------------------------------------------------------------------
__device__ __forceinline__ float4 ldcg4(const float* p){
    float4 v;
    asm volatile("ld.global.cg.v4.f32 {%0,%1,%2,%3},[%4];"
                 : "=f"(v.x),"=f"(v.y),"=f"(v.z),"=f"(v.w) : "l"(p));
    return v;
}
__device__ __forceinline__ float sigm(float x){ return 1.f/(1.f+__expf(-x)); }
__device__ __forceinline__ float tanh_e(float x){ return 2.f/(1.f+__expf(-2.f*x)) - 1.f; }

// ---------------------------------------------------------------------------
__global__ void init_bar_kernel(){
    g_bar[0] = 0u; g_bar[1] = 0u;
}

// ---------------------------------------------------------------------------
// Embedding gather: g_xA[bt][:] = emb[ids[bt]][:]
// ---------------------------------------------------------------------------
__global__ void embed_kernel(const int* __restrict__ ids,
                             const float* __restrict__ emb){
    int bt = blockIdx.x;
    int id = ids[bt];
    const float4* s = reinterpret_cast<const float4*>(emb + (size_t)id * HIDn);
    float4*       d = reinterpret_cast<float4*>(g_xA + (size_t)bt * HIDn);
    d[threadIdx.x] = s[threadIdx.x];
}

// ---------------------------------------------------------------------------
// Input projection: xp[dir][m][g] = sum_k x[m][k]*W[n][k] + bi[n] + bh[n]
// (n = dir*1024+g).  C(32768x2048) = A(32768x512) * W(2048x512)^T.
// 64x64x32 tiles, 256 threads, 4x4 register tile.
// ---------------------------------------------------------------------------
__global__ __launch_bounds__(256)
void gemm_xp_kernel(int layer, const float* __restrict__ W,
                    const float* __restrict__ bi, const float* __restrict__ bh){
    const float* __restrict__ A = layer ? g_xB : g_xA;
    __shared__ __align__(16) float As[32][68];   // [k][m]
    __shared__ __align__(16) float Bs[32][68];   // [k][n]
    int tid = threadIdx.x;
    int tx = tid & 15, ty = tid >> 4;
    int m0 = blockIdx.y << 6, n0 = blockIdx.x << 6;

    float acc[4][4];
    #pragma unroll
    for (int i=0;i<4;i++)
        #pragma unroll
        for (int j=0;j<4;j++) acc[i][j]=0.f;

    for (int k0 = 0; k0 < HIDn; k0 += 32){
        #pragma unroll
        for (int r = 0; r < 2; ++r){
            int idx = tid + (r<<8);            // 0..511 float4 slots
            int mm = idx >> 3;                 // 0..63
            int qq = (idx & 7) << 2;           // 0..28
            float4 av = *reinterpret_cast<const float4*>(A + (size_t)(m0+mm)*HIDn + k0 + qq);
            As[qq+0][mm]=av.x; As[qq+1][mm]=av.y; As[qq+2][mm]=av.z; As[qq+3][mm]=av.w;
            float4 wv = *reinterpret_cast<const float4*>(W + (size_t)(n0+mm)*HIDn + k0 + qq);
            Bs[qq+0][mm]=wv.x; Bs[qq+1][mm]=wv.y; Bs[qq+2][mm]=wv.z; Bs[qq+3][mm]=wv.w;
        }
        __syncthreads();
        #pragma unroll 8
        for (int k=0;k<32;k++){
            float4 av = *reinterpret_cast<const float4*>(&As[k][ty<<2]);
            float4 bv = *reinterpret_cast<const float4*>(&Bs[k][tx<<2]);
            float aa[4] = {av.x, av.y, av.z, av.w};
            float bb[4] = {bv.x, bv.y, bv.z, bv.w};
            #pragma unroll
            for (int i=0;i<4;i++)
                #pragma unroll
                for (int j=0;j<4;j++)
                    acc[i][j] = fmaf(aa[i], bb[j], acc[i][j]);
        }
        __syncthreads();
    }
    int dir = n0 >> 10;                        // 64-wide tiles never straddle 1024
    #pragma unroll
    for (int i=0;i<4;i++){
        int m = m0 + (ty<<2) + i;
        #pragma unroll
        for (int j=0;j<4;j++){
            int n = n0 + (tx<<2) + j;
            int g = n & 1023;
            g_xp[((size_t)dir*BTn + m)*G4n + g] = acc[i][j] + bi[n] + bh[n];
        }
    }
}

// ---------------------------------------------------------------------------
// Persistent bidirectional LSTM layer.
// 128 CTAs = dir(2) x unit-chunk(16 units x16) x batch-chunk(16 batches x4).
// Per step: gates(64 rows x 16 batches) = W_hh(smem) @ h(smem); + xp; nonlin;
// write h to double-buffered global; grid barrier.
// ---------------------------------------------------------------------------
__global__ __launch_bounds__(256)
void lstm_kernel(int layer, const float* __restrict__ whh){
    extern __shared__ __align__(16) float smem[];
    float* w_s = smem;               // [64][WS]
    float* h_s = smem + 64*WS;       // [16][WS]
    float* g_s = smem + 80*WS;       // [64][17]
    float* xout = layer ? g_xA : g_xB;

    const int tid = threadIdx.x;
    const int bid = blockIdx.x;
    const int dir = bid >> 6;
    const int uc  = (bid & 63) >> 2;
    const int bc  = bid & 3;
    const int u0  = uc << 4, b0 = bc << 4;

    // Cache my 64 W_hh rows (lr = q*16+jj -> global row q*256+u0+jj)
    for (int i4 = tid; i4 < 4096; i4 += 256){
        int lr = i4 >> 6;
        int kq = (i4 & 63) << 2;
        int q = lr >> 4, jj = lr & 15;
        float4 v = *reinterpret_cast<const float4*>(
            whh + ((size_t)(dir*G4n + (q<<8) + u0 + jj))*Hn + kq);
        *reinterpret_cast<float4*>(w_s + lr*WS + kq) = v;
    }

    const int rp = tid >> 3;         // 0..31   (matmul: rows rp, rp+32)
    const int bp = tid & 7;          // 0..7    (matmul: batches bp, bp+8)
    const int lb = tid >> 4;         // 0..15   (elementwise batch)
    const int jje = tid & 15;        // 0..15   (elementwise unit)
    const int b = b0 + lb;

    // Zero phase-0 h for my owned (dir, b, u) slice
    g_h[((0*2 + dir)*Bn + b)*Hn + u0 + jje] = 0.f;

    unsigned int* ctr = &g_bar[layer];
    unsigned int gen = 0;
    float c_reg = 0.f;

    const float* w0 = w_s + rp*WS;
    const float* w1 = w_s + (rp+32)*WS;
    const float* h0 = h_s + bp*WS;
    const float* h1 = h_s + (bp+8)*WS;

    // pre-loop barrier: all zero-init visible
    {
        __threadfence(); __syncthreads();
        gen++;
        if (tid == 0){
            atomicAdd(ctr, 1u);
            unsigned int tgt = gen * NBLK;
            while (*(volatile unsigned int*)ctr < tgt) { }
        }
        __syncthreads();
    }

    for (int step = 0; step < Tn; ++step){
        int t = dir ? (Tn-1-step) : step;
        int phase = step & 1;

        // prefetch xp (DRAM latency hidden behind the matmul)
        const float* xpb = g_xp + ((size_t)dir*BTn + (size_t)b*Tn + t)*G4n + (u0 + jje);
        float xgi = xpb[0], xgf = xpb[256], xgg = xpb[512], xgo = xpb[768];

        // load h for my 16 batches (bypass L1: written by other CTAs)
        for (int i4 = tid; i4 < 1024; i4 += 256){
            int hb = i4 >> 6;
            int kq = (i4 & 63) << 2;
            float4 v = ldcg4(g_h + (((size_t)phase*2 + dir)*Bn + b0 + hb)*Hn + kq);
            *reinterpret_cast<float4*>(h_s + hb*WS + kq) = v;
        }
        __syncthreads();

        // gates = W_hh @ h : 4 outputs/thread
        float a00=0.f, a01=0.f, a10=0.f, a11=0.f;
        #pragma unroll 8
        for (int k=0;k<Hn;k+=4){
            float4 wv0 = *reinterpret_cast<const float4*>(w0+k);
            float4 wv1 = *reinterpret_cast<const float4*>(w1+k);
            float4 hv0 = *reinterpret_cast<const float4*>(h0+k);
            float4 hv1 = *reinterpret_cast<const float4*>(h1+k);
            a00=fmaf(wv0.x,hv0.x,a00); a00=fmaf(wv0.y,hv0.y,a00);
            a00=fmaf(wv0.z,hv0.z,a00); a00=fmaf(wv0.w,hv0.w,a00);
            a01=fmaf(wv0.x,hv1.x,a01); a01=fmaf(wv0.y,hv1.y,a01);
            a01=fmaf(wv0.z,hv1.z,a01); a01=fmaf(wv0.w,hv1.w,a01);
            a10=fmaf(wv1.x,hv0.x,a10); a10=fmaf(wv1.y,hv0.y,a10);
            a10=fmaf(wv1.z,hv0.z,a10); a10=fmaf(wv1.w,hv0.w,a10);
            a11=fmaf(wv1.x,hv1.x,a11); a11=fmaf(wv1.y,hv1.y,a11);
            a11=fmaf(wv1.z,hv1.z,a11); a11=fmaf(wv1.w,hv1.w,a11);
        }
        g_s[rp*17 + bp]        = a00;
        g_s[rp*17 + bp + 8]    = a01;
        g_s[(rp+32)*17 + bp]   = a10;
        g_s[(rp+32)*17 + bp+8] = a11;
        __syncthreads();

        // elementwise gate update (thread owns one (b,u); c stays in register)
        float gi = g_s[jje*17      + lb] + xgi;
        float gf = g_s[(16+jje)*17 + lb] + xgf;
        float gg = g_s[(32+jje)*17 + lb] + xgg;
        float go = g_s[(48+jje)*17 + lb] + xgo;
        c_reg = sigm(gf)*c_reg + sigm(gi)*tanh_e(gg);
        float hh = sigm(go)*tanh_e(c_reg);

        g_h[((((step+1)&1)*2 + dir)*Bn + b)*Hn + u0 + jje] = hh;
        xout[((size_t)b*Tn + t)*HIDn + dir*Hn + u0 + jje] = hh;

        // grid barrier
        __threadfence(); __syncthreads();
        gen++;
        if (tid == 0){
            atomicAdd(ctr, 1u);
            unsigned int tgt = gen * NBLK;
            while (*(volatile unsigned int*)ctr < tgt) { }
        }
        __syncthreads();
    }
}

// ---------------------------------------------------------------------------
// Logits: logits[bt][l] = x[bt][:] . cls_w[l][:] + cls_b[l]   (warp per row)
// ---------------------------------------------------------------------------
__global__ __launch_bounds__(256)
void logits_kernel(const float* __restrict__ cls_w, const float* __restrict__ cls_b){
    int row  = (blockIdx.x << 3) + (threadIdx.x >> 5);   // bt
    int lane = threadIdx.x & 31;
    const float* xr = g_xA + (size_t)row*HIDn + lane*16;
    float xv[16];
    #pragma unroll
    for (int q=0;q<4;q++){
        float4 v = *reinterpret_cast<const float4*>(xr + q*4);
        xv[q*4+0]=v.x; xv[q*4+1]=v.y; xv[q*4+2]=v.z; xv[q*4+3]=v.w;
    }
    float myout = 0.f;
    #pragma unroll
    for (int l=0;l<NLn;l++){
        const float* wr = cls_w + l*HIDn + lane*16;
        float p = 0.f;
        #pragma unroll
        for (int j=0;j<16;j++) p = fmaf(xv[j], __ldg(wr+j), p);
        #pragma unroll
        for (int o=16;o;o>>=1) p += __shfl_xor_sync(0xffffffffu, p, o);
        if (lane == l) myout = p + cls_b[l];
    }
    if (lane < NLn) g_logits[(size_t)row*NLn + lane] = myout;
}

// ---------------------------------------------------------------------------
// CRF: one warp per batch element. lanes 0..8 hold states.
// ---------------------------------------------------------------------------
__global__ void crf_kernel(const int* __restrict__ labels,
                           const float* __restrict__ start_trans,
                           const float* __restrict__ end_trans,
                           const float* __restrict__ trans){
    int b    = blockIdx.x;
    int lane = threadIdx.x;
    __shared__ float tr_s[NLn*NLn];
    for (int i = lane; i < NLn*NLn; i += 32) tr_s[i] = trans[i];
    __syncwarp();

    bool act = lane < NLn;
    float tr[NLn];
    #pragma unroll
    for (int k=0;k<NLn;k++) tr[k] = act ? trans[k*NLn + lane] : 0.f;

    const float* lg = g_logits + (size_t)b*Tn*NLn;
    const int*   lb = labels   + (size_t)b*Tn;

    float em    = act ? lg[lane] : -1e30f;
    float alpha = act ? (start_trans[lane] + em) : -1e30f;
    int prev = lb[0];
    float num = __shfl_sync(0xffffffffu, em, prev) + start_trans[prev];

    for (int t=1;t<Tn;t++){
        em = act ? lg[t*NLn + lane] : -1e30f;
        int tag = lb[t];
        float v[NLn], m = -1e30f;
        #pragma unroll
        for (int k=0;k<NLn;k++){
            float ak = __shfl_sync(0xffffffffu, alpha, k);
            v[k] = ak + tr[k];
            m = fmaxf(m, v[k]);
        }
        float s = 0.f;
        #pragma unroll
        for (int k=0;k<NLn;k++) s += __expf(v[k]-m);
        float na = m + __logf(s) + em;
        num += tr_s[prev*NLn + tag] + __shfl_sync(0xffffffffu, em, tag);
        alpha = act ? na : -1e30f;
        prev = tag;
    }
    float fa = act ? (alpha + end_trans[lane]) : -1e30f;
    float m = fa;
    #pragma unroll
    for (int o=16;o;o>>=1) m = fmaxf(m, __shfl_xor_sync(0xffffffffu, m, o));
    float s = act ? __expf(fa - m) : 0.f;
    #pragma unroll
    for (int o=16;o;o>>=1) s += __shfl_xor_sync(0xffffffffu, s, o);
    float denom = m + __logf(s);
    num += end_trans[prev];
    if (lane == 0) g_crf[b] = num - denom;
}

__global__ void finish_kernel(float* out){
    int lane = threadIdx.x;                 // 32
    float s = g_crf[lane] + g_crf[lane+32];
    #pragma unroll
    for (int o=16;o;o>>=1) s += __shfl_xor_sync(0xffffffffu, s, o);
    if (lane == 0) out[0] = -s;
}

// ---------------------------------------------------------------------------
extern "C" void kernel_launch(void* const* d_in, const int* in_sizes, int n_in,
                              void* d_out, int out_size){
    const int*   ids         = (const int*)  d_in[0];
    const int*   labels      = (const int*)  d_in[1];
    const float* emb         = (const float*)d_in[2];
    const float* w_ih        = (const float*)d_in[3];
    const float* w_hh        = (const float*)d_in[4];
    const float* b_ih        = (const float*)d_in[5];
    const float* b_hh        = (const float*)d_in[6];
    const float* cls_w       = (const float*)d_in[7];
    const float* cls_b       = (const float*)d_in[8];
    const float* start_trans = (const float*)d_in[9];
    const float* end_trans   = (const float*)d_in[10];
    const float* trans       = (const float*)d_in[11];
    float* out = (float*)d_out;

    cudaFuncSetAttribute(lstm_kernel,
                         cudaFuncAttributeMaxDynamicSharedMemorySize, LSTM_SMEM);

    init_bar_kernel<<<1,1>>>();
    embed_kernel<<<BTn,128>>>(ids, emb);

    for (int layer = 0; layer < 2; ++layer){
        gemm_xp_kernel<<<dim3(32,512),256>>>(layer,
            w_ih + (size_t)layer*2048*HIDn,
            b_ih + (size_t)layer*2048,
            b_hh + (size_t)layer*2048);
        lstm_kernel<<<NBLK,256,LSTM_SMEM>>>(layer,
            w_hh + (size_t)layer*2*G4n*Hn);
    }

    logits_kernel<<<BTn/8,256>>>(cls_w, cls_b);
    crf_kernel<<<Bn,32>>>(labels, start_trans, end_trans, trans);
    finish_kernel<<<1,32>>>(out);
}

// round 7
// speedup vs baseline: 1.3985x; 1.3985x over previous
#include <cuda_runtime.h>
#include <cuda_bf16.h>
#include <math.h>
#include <stdint.h>

// ---------------------------------------------------------------------------
// Problem constants
// ---------------------------------------------------------------------------
#define Bn    64
#define Tn    512
#define HIDn  512
#define Hn    256
#define G4n   1024           // 4*H
#define NLn   9
#define BTn   (Bn*Tn)        // 32768
#define NBLK  128            // persistent LSTM CTAs (<=148 SMs -> co-resident)
#define WS    260            // padded smem row stride (floats): 16B aligned, 4-bank skew
#define LSTM_SMEM ((80*WS + 64*17) * 4)   // w_s(64 rows)+h_s(16 rows)+g_s = 87552 B

typedef unsigned long long u64;

// ---------------------------------------------------------------------------
// Device scratch (cudaMalloc forbidden -> module globals)
// ---------------------------------------------------------------------------
__device__ float g_xA[BTn*HIDn];                  // 64 MB
__device__ float g_xB[BTn*HIDn];                  // 64 MB
__device__ __nv_bfloat16 g_xh[BTn*HIDn];          // 32 MB (bf16 GEMM A)
__device__ __nv_bfloat16 g_wh[2048*HIDn];         //  2 MB (bf16 GEMM B = W_ih layer)
__device__ float g_xp[2ll*BTn*G4n];               // 256 MB  [dir][bt][gate-row]
__device__ float g_h[2*2*Bn*Hn];                  // [phase][dir][b][u] double-buffered
__device__ float g_logits[BTn*NLn];
__device__ float g_crf[Bn];
__device__ unsigned int g_bar[2];

// ---------------------------------------------------------------------------
__device__ __forceinline__ float4 ldcg4(const float* p){
    float4 v;
    asm volatile("ld.global.cg.v4.f32 {%0,%1,%2,%3},[%4];"
                 : "=f"(v.x),"=f"(v.y),"=f"(v.z),"=f"(v.w) : "l"(p));
    return v;
}
__device__ __forceinline__ float sigm(float x){ return 1.f/(1.f+__expf(-x)); }
__device__ __forceinline__ float tanh_e(float x){ return 2.f/(1.f+__expf(-2.f*x)) - 1.f; }

__device__ __forceinline__ u64 fma2(u64 a, u64 b, u64 c){
    u64 d;
    asm("fma.rn.f32x2 %0, %1, %2, %3;" : "=l"(d) : "l"(a), "l"(b), "l"(c));
    return d;
}
__device__ __forceinline__ float f2sum(u64 v){
    float lo, hi;
    asm("mov.b64 {%0,%1}, %2;" : "=f"(lo), "=f"(hi) : "l"(v));
    return lo + hi;
}

// ---------------------------------------------------------------------------
__global__ void init_bar_kernel(){
    g_bar[0] = 0u; g_bar[1] = 0u;
}

// ---------------------------------------------------------------------------
// Embedding gather: g_xA[bt][:] = emb[ids[bt]][:]
// ---------------------------------------------------------------------------
__global__ void embed_kernel(const int* __restrict__ ids,
                             const float* __restrict__ emb){
    int bt = blockIdx.x;
    int id = ids[bt];
    const float4* s = reinterpret_cast<const float4*>(emb + (size_t)id * HIDn);
    float4*       d = reinterpret_cast<float4*>(g_xA + (size_t)bt * HIDn);
    d[threadIdx.x] = s[threadIdx.x];
}

// ---------------------------------------------------------------------------
// fp32 -> bf16 converts (GEMM operands)
// ---------------------------------------------------------------------------
__global__ __launch_bounds__(256)
void conv_x_kernel(int layer){
    const float* __restrict__ src = layer ? g_xB : g_xA;
    size_t i = (((size_t)blockIdx.x << 8) + threadIdx.x) << 3;   // 8 elems/thread
    float4 v0 = *reinterpret_cast<const float4*>(src + i);
    float4 v1 = *reinterpret_cast<const float4*>(src + i + 4);
    __nv_bfloat162 o[4];
    o[0] = __floats2bfloat162_rn(v0.x, v0.y);
    o[1] = __floats2bfloat162_rn(v0.z, v0.w);
    o[2] = __floats2bfloat162_rn(v1.x, v1.y);
    o[3] = __floats2bfloat162_rn(v1.z, v1.w);
    *reinterpret_cast<uint4*>(g_xh + i) = *reinterpret_cast<uint4*>(o);
}
__global__ __launch_bounds__(256)
void conv_w_kernel(const float* __restrict__ W){
    size_t i = (((size_t)blockIdx.x << 8) + threadIdx.x) << 3;
    float4 v0 = *reinterpret_cast<const float4*>(W + i);
    float4 v1 = *reinterpret_cast<const float4*>(W + i + 4);
    __nv_bfloat162 o[4];
    o[0] = __floats2bfloat162_rn(v0.x, v0.y);
    o[1] = __floats2bfloat162_rn(v0.z, v0.w);
    o[2] = __floats2bfloat162_rn(v1.x, v1.y);
    o[3] = __floats2bfloat162_rn(v1.z, v1.w);
    *reinterpret_cast<uint4*>(g_wh + i) = *reinterpret_cast<uint4*>(o);
}

// ---------------------------------------------------------------------------
// Input projection on tensor cores (bf16 mma.sync, fp32 accumulate):
// C(32768 x 2048) = A(32768x512) * W(2048x512)^T ; xp += bi + bh.
// CTA tile 128x128x32, 8 warps in 2x4, warp tile 64x32, m16n8k16.
// smem row stride 40 bf16 (80 B): conflict-free ldmatrix (8 rows span all
// eight 16B bank groups: 0,80,32,112,64,16,96,48 mod 128).
// ---------------------------------------------------------------------------
#define ASTR 40

__global__ __launch_bounds__(256)
void gemm_xp_mma(const float* __restrict__ bi, const float* __restrict__ bh){
    __shared__ __align__(16) __nv_bfloat16 As[128*ASTR];
    __shared__ __align__(16) __nv_bfloat16 Bs[128*ASTR];

    const int tid  = threadIdx.x;
    const int wid  = tid >> 5;
    const int lane = tid & 31;
    const int m0 = blockIdx.y << 7;
    const int n0 = blockIdx.x << 7;
    const int wm = wid >> 2;          // 0..1
    const int wn = wid & 3;           // 0..3

    float acc[4][4][4];
    #pragma unroll
    for (int mi=0;mi<4;mi++)
        #pragma unroll
        for (int ni=0;ni<4;ni++)
            #pragma unroll
            for (int r=0;r<4;r++) acc[mi][ni][r]=0.f;

    // G->S mapping: thread loads 16 consecutive bf16 (32B) of one row
    const int lrow = tid >> 1;
    const int lqo  = (tid & 1) << 4;            // bf16 offset 0 or 16
    const __nv_bfloat16* gA = g_xh + (size_t)(m0 + lrow)*HIDn + lqo;
    const __nv_bfloat16* gB = g_wh + (size_t)(n0 + lrow)*HIDn + lqo;

    uint4 pa0 = *reinterpret_cast<const uint4*>(gA);
    uint4 pa1 = *reinterpret_cast<const uint4*>(gA + 8);
    uint4 pb0 = *reinterpret_cast<const uint4*>(gB);
    uint4 pb1 = *reinterpret_cast<const uint4*>(gB + 8);

    // ldmatrix source addresses (shared-space u32)
    uint32_t aAddr[4], bAddr[4];
    {
        int r16 = lane & 15;
        #pragma unroll
        for (int mi=0;mi<4;mi++){
            int row = (wm<<6) + (mi<<4) + r16;
            int col = (lane>>4) << 3;
            aAddr[mi] = (uint32_t)__cvta_generic_to_shared(As + row*ASTR + col);
        }
        #pragma unroll
        for (int ni=0;ni<4;ni++){
            int row = (wn<<5) + (ni<<3) + (r16 & 7);
            int col = ((r16>>3) & 1) << 3;
            bAddr[ni] = (uint32_t)__cvta_generic_to_shared(Bs + row*ASTR + col);
        }
    }
    uint32_t sa = (uint32_t)__cvta_generic_to_shared(As + lrow*ASTR + lqo);
    uint32_t sb = (uint32_t)__cvta_generic_to_shared(Bs + lrow*ASTR + lqo);

    for (int it = 0; it < 16; ++it){
        asm volatile("st.shared.v4.b32 [%0], {%1,%2,%3,%4};" ::
            "r"(sa), "r"(pa0.x),"r"(pa0.y),"r"(pa0.z),"r"(pa0.w));
        asm volatile("st.shared.v4.b32 [%0], {%1,%2,%3,%4};" ::
            "r"(sa+16), "r"(pa1.x),"r"(pa1.y),"r"(pa1.z),"r"(pa1.w));
        asm volatile("st.shared.v4.b32 [%0], {%1,%2,%3,%4};" ::
            "r"(sb), "r"(pb0.x),"r"(pb0.y),"r"(pb0.z),"r"(pb0.w));
        asm volatile("st.shared.v4.b32 [%0], {%1,%2,%3,%4};" ::
            "r"(sb+16), "r"(pb1.x),"r"(pb1.y),"r"(pb1.z),"r"(pb1.w));
        __syncthreads();

        if (it < 15){
            const __nv_bfloat16* nA = gA + (it+1)*32;
            const __nv_bfloat16* nB = gB + (it+1)*32;
            pa0 = *reinterpret_cast<const uint4*>(nA);
            pa1 = *reinterpret_cast<const uint4*>(nA + 8);
            pb0 = *reinterpret_cast<const uint4*>(nB);
            pb1 = *reinterpret_cast<const uint4*>(nB + 8);
        }

        #pragma unroll
        for (int kk = 0; kk < 2; ++kk){
            uint32_t af[4][4];
            #pragma unroll
            for (int mi=0;mi<4;mi++){
                asm volatile("ldmatrix.sync.aligned.m8n8.x4.shared.b16 "
                    "{%0,%1,%2,%3}, [%4];"
                    : "=r"(af[mi][0]),"=r"(af[mi][1]),"=r"(af[mi][2]),"=r"(af[mi][3])
                    : "r"(aAddr[mi] + kk*32));
            }
            uint32_t bf[4][2];
            #pragma unroll
            for (int ni=0;ni<4;ni++){
                asm volatile("ldmatrix.sync.aligned.m8n8.x2.shared.b16 "
                    "{%0,%1}, [%2];"
                    : "=r"(bf[ni][0]),"=r"(bf[ni][1])
                    : "r"(bAddr[ni] + kk*32));
            }
            #pragma unroll
            for (int mi=0;mi<4;mi++){
                #pragma unroll
                for (int ni=0;ni<4;ni++){
                    asm volatile(
                        "mma.sync.aligned.m16n8k16.row.col.f32.bf16.bf16.f32 "
                        "{%0,%1,%2,%3}, {%4,%5,%6,%7}, {%8,%9}, {%0,%1,%2,%3};"
                        : "+f"(acc[mi][ni][0]),"+f"(acc[mi][ni][1]),
                          "+f"(acc[mi][ni][2]),"+f"(acc[mi][ni][3])
                        : "r"(af[mi][0]),"r"(af[mi][1]),"r"(af[mi][2]),"r"(af[mi][3]),
                          "r"(bf[ni][0]),"r"(bf[ni][1]));
                }
            }
        }
        __syncthreads();
    }

    // Epilogue: add bias, store fp32 to g_xp[dir][bt][g]
    const int dir = n0 >> 10;                 // 128-wide N tiles never straddle 1024
    #pragma unroll
    for (int ni=0;ni<4;ni++){
        int ncol = n0 + (wn<<5) + (ni<<3) + ((lane & 3) << 1);
        float bs0 = bi[ncol]   + bh[ncol];
        float bs1 = bi[ncol+1] + bh[ncol+1];
        int g = ncol & 1023;
        #pragma unroll
        for (int mi=0;mi<4;mi++){
            int mrow = m0 + (wm<<6) + (mi<<4) + (lane >> 2);
            float2 v0 = make_float2(acc[mi][ni][0] + bs0, acc[mi][ni][1] + bs1);
            float2 v1 = make_float2(acc[mi][ni][2] + bs0, acc[mi][ni][3] + bs1);
            *reinterpret_cast<float2*>(&g_xp[((size_t)dir*BTn + mrow)*G4n + g])   = v0;
            *reinterpret_cast<float2*>(&g_xp[((size_t)dir*BTn + mrow+8)*G4n + g]) = v1;
        }
    }
}

// ---------------------------------------------------------------------------
// Persistent bidirectional LSTM layer (fp32, packed f32x2 FMA mainloop).
// 128 CTAs = dir(2) x unit-chunk(16 units x16) x batch-chunk(16 batches x4).
// ---------------------------------------------------------------------------
__global__ __launch_bounds__(256)
void lstm_kernel(int layer, const float* __restrict__ whh){
    extern __shared__ __align__(16) float smem[];
    float* w_s = smem;               // [64][WS]
    float* h_s = smem + 64*WS;       // [16][WS]
    float* g_s = smem + 80*WS;       // [64][17]
    float* xout = layer ? g_xA : g_xB;

    const int tid = threadIdx.x;
    const int bid = blockIdx.x;
    const int dir = bid >> 6;
    const int uc  = (bid & 63) >> 2;
    const int bc  = bid & 3;
    const int u0  = uc << 4, b0 = bc << 4;

    // Cache my 64 W_hh rows (lr = q*16+jj -> global row q*256+u0+jj)
    for (int i4 = tid; i4 < 4096; i4 += 256){
        int lr = i4 >> 6;
        int kq = (i4 & 63) << 2;
        int q = lr >> 4, jj = lr & 15;
        float4 v = *reinterpret_cast<const float4*>(
            whh + ((size_t)(dir*G4n + (q<<8) + u0 + jj))*Hn + kq);
        *reinterpret_cast<float4*>(w_s + lr*WS + kq) = v;
    }

    const int rp = tid >> 3;         // 0..31   (matmul: rows rp, rp+32)
    const int bp = tid & 7;          // 0..7    (matmul: batches bp, bp+8)
    const int lb = tid >> 4;         // 0..15   (elementwise batch)
    const int jje = tid & 15;        // 0..15   (elementwise unit)
    const int b = b0 + lb;

    g_h[((0*2 + dir)*Bn + b)*Hn + u0 + jje] = 0.f;

    unsigned int* ctr = &g_bar[layer];
    unsigned int gen = 0;
    float c_reg = 0.f;

    const float* w0 = w_s + rp*WS;
    const float* w1 = w_s + (rp+32)*WS;
    const float* h0 = h_s + bp*WS;
    const float* h1 = h_s + (bp+8)*WS;

    // pre-loop barrier: zero-init visible everywhere
    {
        __threadfence(); __syncthreads();
        gen++;
        if (tid == 0){
            atomicAdd(ctr, 1u);
            unsigned int tgt = gen * NBLK;
            while (*(volatile unsigned int*)ctr < tgt) { }
        }
        __syncthreads();
    }

    for (int step = 0; step < Tn; ++step){
        int t = dir ? (Tn-1-step) : step;
        int phase = step & 1;

        // prefetch xp (latency hidden behind the matmul)
        const float* xpb = g_xp + ((size_t)dir*BTn + (size_t)b*Tn + t)*G4n + (u0 + jje);
        float xgi = xpb[0], xgf = xpb[256], xgg = xpb[512], xgo = xpb[768];

        // load h for my 16 batches (bypass L1: written by other CTAs)
        for (int i4 = tid; i4 < 1024; i4 += 256){
            int hb = i4 >> 6;
            int kq = (i4 & 63) << 2;
            float4 v = ldcg4(g_h + (((size_t)phase*2 + dir)*Bn + b0 + hb)*Hn + kq);
            *reinterpret_cast<float4*>(h_s + hb*WS + kq) = v;
        }
        __syncthreads();

        // gates = W_hh @ h : 4 outputs/thread, packed f32x2 FMAs
        u64 A00=0ull, A01=0ull, A10=0ull, A11=0ull;
        #pragma unroll 8
        for (int k=0;k<Hn;k+=4){
            ulonglong2 wv0 = *reinterpret_cast<const ulonglong2*>(w0+k);
            ulonglong2 wv1 = *reinterpret_cast<const ulonglong2*>(w1+k);
            ulonglong2 hv0 = *reinterpret_cast<const ulonglong2*>(h0+k);
            ulonglong2 hv1 = *reinterpret_cast<const ulonglong2*>(h1+k);
            A00 = fma2(wv0.x, hv0.x, A00); A00 = fma2(wv0.y, hv0.y, A00);
            A01 = fma2(wv0.x, hv1.x, A01); A01 = fma2(wv0.y, hv1.y, A01);
            A10 = fma2(wv1.x, hv0.x, A10); A10 = fma2(wv1.y, hv0.y, A10);
            A11 = fma2(wv1.x, hv1.x, A11); A11 = fma2(wv1.y, hv1.y, A11);
        }
        g_s[rp*17 + bp]        = f2sum(A00);
        g_s[rp*17 + bp + 8]    = f2sum(A01);
        g_s[(rp+32)*17 + bp]   = f2sum(A10);
        g_s[(rp+32)*17 + bp+8] = f2sum(A11);
        __syncthreads();

        // elementwise gate update (thread owns one (b,u); c stays in register)
        float gi = g_s[jje*17      + lb] + xgi;
        float gf = g_s[(16+jje)*17 + lb] + xgf;
        float gg = g_s[(32+jje)*17 + lb] + xgg;
        float go = g_s[(48+jje)*17 + lb] + xgo;
        c_reg = sigm(gf)*c_reg + sigm(gi)*tanh_e(gg);
        float hh = sigm(go)*tanh_e(c_reg);

        g_h[((((step+1)&1)*2 + dir)*Bn + b)*Hn + u0 + jje] = hh;
        xout[((size_t)b*Tn + t)*HIDn + dir*Hn + u0 + jje] = hh;

        // grid barrier
        __threadfence(); __syncthreads();
        gen++;
        if (tid == 0){
            atomicAdd(ctr, 1u);
            unsigned int tgt = gen * NBLK;
            while (*(volatile unsigned int*)ctr < tgt) { }
        }
        __syncthreads();
    }
}

// ---------------------------------------------------------------------------
// Logits: logits[bt][l] = x[bt][:] . cls_w[l][:] + cls_b[l]   (warp per row)
// ---------------------------------------------------------------------------
__global__ __launch_bounds__(256)
void logits_kernel(const float* __restrict__ cls_w, const float* __restrict__ cls_b){
    int row  = (blockIdx.x << 3) + (threadIdx.x >> 5);   // bt
    int lane = threadIdx.x & 31;
    const float* xr = g_xA + (size_t)row*HIDn + lane*16;
    float xv[16];
    #pragma unroll
    for (int q=0;q<4;q++){
        float4 v = *reinterpret_cast<const float4*>(xr + q*4);
        xv[q*4+0]=v.x; xv[q*4+1]=v.y; xv[q*4+2]=v.z; xv[q*4+3]=v.w;
    }
    float myout = 0.f;
    #pragma unroll
    for (int l=0;l<NLn;l++){
        const float* wr = cls_w + l*HIDn + lane*16;
        float p = 0.f;
        #pragma unroll
        for (int j=0;j<16;j++) p = fmaf(xv[j], __ldg(wr+j), p);
        #pragma unroll
        for (int o=16;o;o>>=1) p += __shfl_xor_sync(0xffffffffu, p, o);
        if (lane == l) myout = p + cls_b[l];
    }
    if (lane < NLn) g_logits[(size_t)row*NLn + lane] = myout;
}

// ---------------------------------------------------------------------------
// CRF: one warp per batch element. lanes 0..8 hold states.
// ---------------------------------------------------------------------------
__global__ void crf_kernel(const int* __restrict__ labels,
                           const float* __restrict__ start_trans,
                           const float* __restrict__ end_trans,
                           const float* __restrict__ trans){
    int b    = blockIdx.x;
    int lane = threadIdx.x;
    __shared__ float tr_s[NLn*NLn];
    for (int i = lane; i < NLn*NLn; i += 32) tr_s[i] = trans[i];
    __syncwarp();

    bool act = lane < NLn;
    float tr[NLn];
    #pragma unroll
    for (int k=0;k<NLn;k++) tr[k] = act ? trans[k*NLn + lane] : 0.f;

    const float* lg = g_logits + (size_t)b*Tn*NLn;
    const int*   lb = labels   + (size_t)b*Tn;

    float em    = act ? lg[lane] : -1e30f;
    float alpha = act ? (start_trans[lane] + em) : -1e30f;
    int prev = lb[0];
    float num = __shfl_sync(0xffffffffu, em, prev) + start_trans[prev];

    for (int t=1;t<Tn;t++){
        em = act ? lg[t*NLn + lane] : -1e30f;
        int tag = lb[t];
        float v[NLn], m = -1e30f;
        #pragma unroll
        for (int k=0;k<NLn;k++){
            float ak = __shfl_sync(0xffffffffu, alpha, k);
            v[k] = ak + tr[k];
            m = fmaxf(m, v[k]);
        }
        float s = 0.f;
        #pragma unroll
        for (int k=0;k<NLn;k++) s += __expf(v[k]-m);
        float na = m + __logf(s) + em;
        num += tr_s[prev*NLn + tag] + __shfl_sync(0xffffffffu, em, tag);
        alpha = act ? na : -1e30f;
        prev = tag;
    }
    float fa = act ? (alpha + end_trans[lane]) : -1e30f;
    float m = fa;
    #pragma unroll
    for (int o=16;o;o>>=1) m = fmaxf(m, __shfl_xor_sync(0xffffffffu, m, o));
    float s = act ? __expf(fa - m) : 0.f;
    #pragma unroll
    for (int o=16;o;o>>=1) s += __shfl_xor_sync(0xffffffffu, s, o);
    float denom = m + __logf(s);
    num += end_trans[prev];
    if (lane == 0) g_crf[b] = num - denom;
}

__global__ void finish_kernel(float* out){
    int lane = threadIdx.x;                 // 32
    float s = g_crf[lane] + g_crf[lane+32];
    #pragma unroll
    for (int o=16;o;o>>=1) s += __shfl_xor_sync(0xffffffffu, s, o);
    if (lane == 0) out[0] = -s;
}

// ---------------------------------------------------------------------------
extern "C" void kernel_launch(void* const* d_in, const int* in_sizes, int n_in,
                              void* d_out, int out_size){
    const int*   ids         = (const int*)  d_in[0];
    const int*   labels      = (const int*)  d_in[1];
    const float* emb         = (const float*)d_in[2];
    const float* w_ih        = (const float*)d_in[3];
    const float* w_hh        = (const float*)d_in[4];
    const float* b_ih        = (const float*)d_in[5];
    const float* b_hh        = (const float*)d_in[6];
    const float* cls_w       = (const float*)d_in[7];
    const float* cls_b       = (const float*)d_in[8];
    const float* start_trans = (const float*)d_in[9];
    const float* end_trans   = (const float*)d_in[10];
    const float* trans       = (const float*)d_in[11];
    float* out = (float*)d_out;

    cudaFuncSetAttribute(lstm_kernel,
                         cudaFuncAttributeMaxDynamicSharedMemorySize, LSTM_SMEM);

    init_bar_kernel<<<1,1>>>();
    embed_kernel<<<BTn,128>>>(ids, emb);

    for (int layer = 0; layer < 2; ++layer){
        conv_x_kernel<<<(BTn*HIDn)/2048, 256>>>(layer);
        conv_w_kernel<<<(2048*HIDn)/2048, 256>>>(w_ih + (size_t)layer*2048*HIDn);
        gemm_xp_mma<<<dim3(16,256),256>>>(
            b_ih + (size_t)layer*2048,
            b_hh + (size_t)layer*2048);
        lstm_kernel<<<NBLK,256,LSTM_SMEM>>>(layer,
            w_hh + (size_t)layer*2*G4n*Hn);
    }

    logits_kernel<<<BTn/8,256>>>(cls_w, cls_b);
    crf_kernel<<<Bn,32>>>(labels, start_trans, end_trans, trans);
    finish_kernel<<<1,32>>>(out);
}

// round 8
// speedup vs baseline: 3.1411x; 2.2461x over previous
#include <cuda_runtime.h>
#include <cuda_bf16.h>
#include <math.h>
#include <stdint.h>

// ---------------------------------------------------------------------------
// Problem constants
// ---------------------------------------------------------------------------
#define Bn    64
#define Tn    512
#define HIDn  512
#define Hn    256
#define G4n   1024           // 4*H
#define NLn   9
#define BTn   (Bn*Tn)        // 32768

typedef unsigned long long u64;

// ---------------------------------------------------------------------------
// Device scratch (cudaMalloc forbidden -> module globals)
// ---------------------------------------------------------------------------
__device__ float g_xA[BTn*HIDn];                  // 64 MB
__device__ float g_xB[BTn*HIDn];                  // 64 MB
__device__ __nv_bfloat16 g_xh[BTn*HIDn];          // 32 MB (bf16 GEMM A)
__device__ __nv_bfloat16 g_wh[2048*HIDn];         //  2 MB (bf16 GEMM B = W_ih layer)
__device__ float g_xp[2ll*BTn*G4n];               // 256 MB [dir][bt][gate-row]
__device__ float g_logits[BTn*NLn];
__device__ float g_crf[Bn];

// ---------------------------------------------------------------------------
__device__ __forceinline__ float sigm(float x){ return 1.f/(1.f+__expf(-x)); }
__device__ __forceinline__ float tanh_e(float x){ return 2.f/(1.f+__expf(-2.f*x)) - 1.f; }

// ---------------------------------------------------------------------------
// Embedding gather: g_xA[bt][:] = emb[ids[bt]][:]
// ---------------------------------------------------------------------------
__global__ void embed_kernel(const int* __restrict__ ids,
                             const float* __restrict__ emb){
    int bt = blockIdx.x;
    int id = ids[bt];
    const float4* s = reinterpret_cast<const float4*>(emb + (size_t)id * HIDn);
    float4*       d = reinterpret_cast<float4*>(g_xA + (size_t)bt * HIDn);
    d[threadIdx.x] = s[threadIdx.x];
}

// ---------------------------------------------------------------------------
// fp32 -> bf16 converts (GEMM operands)
// ---------------------------------------------------------------------------
__global__ __launch_bounds__(256)
void conv_x_kernel(int layer){
    const float* __restrict__ src = layer ? g_xB : g_xA;
    size_t i = (((size_t)blockIdx.x << 8) + threadIdx.x) << 3;   // 8 elems/thread
    float4 v0 = *reinterpret_cast<const float4*>(src + i);
    float4 v1 = *reinterpret_cast<const float4*>(src + i + 4);
    __nv_bfloat162 o[4];
    o[0] = __floats2bfloat162_rn(v0.x, v0.y);
    o[1] = __floats2bfloat162_rn(v0.z, v0.w);
    o[2] = __floats2bfloat162_rn(v1.x, v1.y);
    o[3] = __floats2bfloat162_rn(v1.z, v1.w);
    *reinterpret_cast<uint4*>(g_xh + i) = *reinterpret_cast<uint4*>(o);
}
__global__ __launch_bounds__(256)
void conv_w_kernel(const float* __restrict__ W){
    size_t i = (((size_t)blockIdx.x << 8) + threadIdx.x) << 3;
    float4 v0 = *reinterpret_cast<const float4*>(W + i);
    float4 v1 = *reinterpret_cast<const float4*>(W + i + 4);
    __nv_bfloat162 o[4];
    o[0] = __floats2bfloat162_rn(v0.x, v0.y);
    o[1] = __floats2bfloat162_rn(v0.z, v0.w);
    o[2] = __floats2bfloat162_rn(v1.x, v1.y);
    o[3] = __floats2bfloat162_rn(v1.z, v1.w);
    *reinterpret_cast<uint4*>(g_wh + i) = *reinterpret_cast<uint4*>(o);
}

// ---------------------------------------------------------------------------
// Input projection on tensor cores (bf16 mma.sync, fp32 accumulate):
// C(32768 x 2048) = A(32768x512) * W(2048x512)^T ; xp += bi + bh.
// (verified rel_err==0 in R6 — unchanged)
// ---------------------------------------------------------------------------
#define ASTR 40

__global__ __launch_bounds__(256)
void gemm_xp_mma(const float* __restrict__ bi, const float* __restrict__ bh){
    __shared__ __align__(16) __nv_bfloat16 As[128*ASTR];
    __shared__ __align__(16) __nv_bfloat16 Bs[128*ASTR];

    const int tid  = threadIdx.x;
    const int wid  = tid >> 5;
    const int lane = tid & 31;
    const int m0 = blockIdx.y << 7;
    const int n0 = blockIdx.x << 7;
    const int wm = wid >> 2;
    const int wn = wid & 3;

    float acc[4][4][4];
    #pragma unroll
    for (int mi=0;mi<4;mi++)
        #pragma unroll
        for (int ni=0;ni<4;ni++)
            #pragma unroll
            for (int r=0;r<4;r++) acc[mi][ni][r]=0.f;

    const int lrow = tid >> 1;
    const int lqo  = (tid & 1) << 4;
    const __nv_bfloat16* gA = g_xh + (size_t)(m0 + lrow)*HIDn + lqo;
    const __nv_bfloat16* gB = g_wh + (size_t)(n0 + lrow)*HIDn + lqo;

    uint4 pa0 = *reinterpret_cast<const uint4*>(gA);
    uint4 pa1 = *reinterpret_cast<const uint4*>(gA + 8);
    uint4 pb0 = *reinterpret_cast<const uint4*>(gB);
    uint4 pb1 = *reinterpret_cast<const uint4*>(gB + 8);

    uint32_t aAddr[4], bAddr[4];
    {
        int r16 = lane & 15;
        #pragma unroll
        for (int mi=0;mi<4;mi++){
            int row = (wm<<6) + (mi<<4) + r16;
            int col = (lane>>4) << 3;
            aAddr[mi] = (uint32_t)__cvta_generic_to_shared(As + row*ASTR + col);
        }
        #pragma unroll
        for (int ni=0;ni<4;ni++){
            int row = (wn<<5) + (ni<<3) + (r16 & 7);
            int col = ((r16>>3) & 1) << 3;
            bAddr[ni] = (uint32_t)__cvta_generic_to_shared(Bs + row*ASTR + col);
        }
    }
    uint32_t sa = (uint32_t)__cvta_generic_to_shared(As + lrow*ASTR + lqo);
    uint32_t sb = (uint32_t)__cvta_generic_to_shared(Bs + lrow*ASTR + lqo);

    for (int it = 0; it < 16; ++it){
        asm volatile("st.shared.v4.b32 [%0], {%1,%2,%3,%4};" ::
            "r"(sa), "r"(pa0.x),"r"(pa0.y),"r"(pa0.z),"r"(pa0.w));
        asm volatile("st.shared.v4.b32 [%0], {%1,%2,%3,%4};" ::
            "r"(sa+16), "r"(pa1.x),"r"(pa1.y),"r"(pa1.z),"r"(pa1.w));
        asm volatile("st.shared.v4.b32 [%0], {%1,%2,%3,%4};" ::
            "r"(sb), "r"(pb0.x),"r"(pb0.y),"r"(pb0.z),"r"(pb0.w));
        asm volatile("st.shared.v4.b32 [%0], {%1,%2,%3,%4};" ::
            "r"(sb+16), "r"(pb1.x),"r"(pb1.y),"r"(pb1.z),"r"(pb1.w));
        __syncthreads();

        if (it < 15){
            const __nv_bfloat16* nA = gA + (it+1)*32;
            const __nv_bfloat16* nB = gB + (it+1)*32;
            pa0 = *reinterpret_cast<const uint4*>(nA);
            pa1 = *reinterpret_cast<const uint4*>(nA + 8);
            pb0 = *reinterpret_cast<const uint4*>(nB);
            pb1 = *reinterpret_cast<const uint4*>(nB + 8);
        }

        #pragma unroll
        for (int kk = 0; kk < 2; ++kk){
            uint32_t af[4][4];
            #pragma unroll
            for (int mi=0;mi<4;mi++){
                asm volatile("ldmatrix.sync.aligned.m8n8.x4.shared.b16 "
                    "{%0,%1,%2,%3}, [%4];"
                    : "=r"(af[mi][0]),"=r"(af[mi][1]),"=r"(af[mi][2]),"=r"(af[mi][3])
                    : "r"(aAddr[mi] + kk*32));
            }
            uint32_t bf[4][2];
            #pragma unroll
            for (int ni=0;ni<4;ni++){
                asm volatile("ldmatrix.sync.aligned.m8n8.x2.shared.b16 "
                    "{%0,%1}, [%2];"
                    : "=r"(bf[ni][0]),"=r"(bf[ni][1])
                    : "r"(bAddr[ni] + kk*32));
            }
            #pragma unroll
            for (int mi=0;mi<4;mi++){
                #pragma unroll
                for (int ni=0;ni<4;ni++){
                    asm volatile(
                        "mma.sync.aligned.m16n8k16.row.col.f32.bf16.bf16.f32 "
                        "{%0,%1,%2,%3}, {%4,%5,%6,%7}, {%8,%9}, {%0,%1,%2,%3};"
                        : "+f"(acc[mi][ni][0]),"+f"(acc[mi][ni][1]),
                          "+f"(acc[mi][ni][2]),"+f"(acc[mi][ni][3])
                        : "r"(af[mi][0]),"r"(af[mi][1]),"r"(af[mi][2]),"r"(af[mi][3]),
                          "r"(bf[ni][0]),"r"(bf[ni][1]));
                }
            }
        }
        __syncthreads();
    }

    const int dir = n0 >> 10;
    #pragma unroll
    for (int ni=0;ni<4;ni++){
        int ncol = n0 + (wn<<5) + (ni<<3) + ((lane & 3) << 1);
        float bs0 = bi[ncol]   + bh[ncol];
        float bs1 = bi[ncol+1] + bh[ncol+1];
        int g = ncol & 1023;
        #pragma unroll
        for (int mi=0;mi<4;mi++){
            int mrow = m0 + (wm<<6) + (mi<<4) + (lane >> 2);
            float2 v0 = make_float2(acc[mi][ni][0] + bs0, acc[mi][ni][1] + bs1);
            float2 v1 = make_float2(acc[mi][ni][2] + bs0, acc[mi][ni][3] + bs1);
            *reinterpret_cast<float2*>(&g_xp[((size_t)dir*BTn + mrow)*G4n + g])   = v0;
            *reinterpret_cast<float2*>(&g_xp[((size_t)dir*BTn + mrow+8)*G4n + g]) = v1;
        }
    }
}

// ---------------------------------------------------------------------------
// Cluster-based persistent bidirectional LSTM.
// 16 clusters x 8 CTAs. Cluster = (dir, 8-batch group). CTA rank owns 32 units
// (all 4 gates = 128 gate rows). W_hh frags live in REGISTERS (bf16, ldmatrix'd
// once). Per step: 16x(ldmatrix B(h) + mma) -> gates; elementwise fp32 (c in
// reg); h bf16 pushed to all 8 CTAs via DSMEM; barrier.cluster.
// Smem (bytes): WSTG[128][264]bf16 @0 (67584) | HBUF[2][8][264]bf16 @67584
// (8448) | GS[128][9]f32 @76032 (4608) | STAGE[8][32]bf16 @80640 (512)
// ---------------------------------------------------------------------------
#define HSTR 264                       // bf16 elements per h/W row (16B-aligned, conflict-free)
#define OFF_W 0
#define OFF_H 67584
#define OFF_G 76032
#define OFF_S 80640
#define LSTM_SMEM 81152
#define HPH 4224                       // bytes per h phase (8*264*2)

__global__ __launch_bounds__(256, 1) __cluster_dims__(8, 1, 1)
void lstm_cluster_kernel(int layer, const float* __restrict__ whh){
    extern __shared__ __align__(16) char sm[];
    float* xout = layer ? g_xA : g_xB;

    const int tid  = threadIdx.x;
    const int wid  = tid >> 5;
    const int lane = tid & 31;
    const int rank = blockIdx.x & 7;          // cluster rank
    const int cid  = blockIdx.x >> 3;
    const int dir  = cid & 1;
    const int bgrp = cid >> 1;                // 0..7
    const int u0   = rank << 5;               // 32 units per CTA

    const uint32_t smb = (uint32_t)__cvta_generic_to_shared(sm);

    // ---- stage W_hh (fp32->bf16) into smem: row r=gate*32+uu, k ----
    for (int idx = tid; idx < 128*64; idx += 256){       // float4 chunks
        int r  = idx >> 6;
        int kq = (idx & 63) << 2;
        int grow = dir*G4n + (r>>5)*Hn + u0 + (r&31);
        float4 v = *reinterpret_cast<const float4*>(whh + (size_t)grow*Hn + kq);
        __nv_bfloat162 o0 = __floats2bfloat162_rn(v.x, v.y);
        __nv_bfloat162 o1 = __floats2bfloat162_rn(v.z, v.w);
        uint2 pk = make_uint2(*reinterpret_cast<uint32_t*>(&o0),
                              *reinterpret_cast<uint32_t*>(&o1));
        *reinterpret_cast<uint2*>(sm + OFF_W + r*(HSTR*2) + kq*2) = pk;
    }
    // ---- zero both h phases ----
    for (int i = tid; i < 2*8*HSTR; i += 256)
        *reinterpret_cast<__nv_bfloat16*>(sm + OFF_H + i*2) = __nv_bfloat16(0.f);
    __syncthreads();

    // ---- preload A (W) fragments into registers: warp w -> rows 16w..16w+15 ----
    uint32_t afr[16][4];
    {
        uint32_t aAddr = smb + OFF_W + (wid*16 + (lane & 15))*(HSTR*2)
                       + (((lane >> 4) << 3) << 1);
        #pragma unroll
        for (int kk = 0; kk < 16; ++kk){
            asm volatile("ldmatrix.sync.aligned.m8n8.x4.shared.b16 "
                "{%0,%1,%2,%3}, [%4];"
                : "=r"(afr[kk][0]),"=r"(afr[kk][1]),"=r"(afr[kk][2]),"=r"(afr[kk][3])
                : "r"(aAddr + kk*32));
        }
    }

    // B (h) ldmatrix base address (phase 0)
    const int r16 = lane & 15;
    const uint32_t bBase = smb + OFF_H + (r16 & 7)*(HSTR*2) + (((r16>>3)&1) << 4);

    // elementwise identity: thread owns (batch bb, unit uu)
    const int bb = tid >> 5;                  // == wid
    const int uu = tid & 31;                  // == lane
    const int bglob = (bgrp << 3) + bb;
    float c_reg = 0.f;

    // gate-smem addresses
    float* gs = reinterpret_cast<float*>(sm + OFF_G);
    const int grow0 = wid*16 + (lane >> 2);
    const int gcol0 = (lane & 3) << 1;

    // ensure all CTAs' h buffers zeroed before anyone's step-0 DSMEM pushes
    asm volatile("barrier.cluster.arrive.aligned;" ::: "memory");
    asm volatile("barrier.cluster.wait.aligned;"   ::: "memory");

    for (int step = 0; step < Tn; ++step){
        const int t = dir ? (Tn-1-step) : step;
        const int p = step & 1;

        // prefetch xp (independent of h; latency hidden behind mma)
        const float* xpb = g_xp + ((size_t)dir*BTn + (size_t)bglob*Tn + t)*G4n + u0 + uu;
        float xgi = __ldcs(xpb);
        float xgf = __ldcs(xpb + 256);
        float xgg = __ldcs(xpb + 512);
        float xgo = __ldcs(xpb + 768);

        // gates[16 rows x 8 batches] = W(regs) @ h(smem)
        float c0=0.f, c1=0.f, c2=0.f, c3=0.f;
        {
            const uint32_t bA = bBase + (uint32_t)p*HPH;
            #pragma unroll
            for (int kk = 0; kk < 16; ++kk){
                uint32_t b0, b1;
                asm volatile("ldmatrix.sync.aligned.m8n8.x2.shared.b16 "
                    "{%0,%1}, [%2];" : "=r"(b0),"=r"(b1) : "r"(bA + kk*32));
                asm volatile(
                    "mma.sync.aligned.m16n8k16.row.col.f32.bf16.bf16.f32 "
                    "{%0,%1,%2,%3}, {%4,%5,%6,%7}, {%8,%9}, {%0,%1,%2,%3};"
                    : "+f"(c0),"+f"(c1),"+f"(c2),"+f"(c3)
                    : "r"(afr[kk][0]),"r"(afr[kk][1]),"r"(afr[kk][2]),"r"(afr[kk][3]),
                      "r"(b0),"r"(b1));
            }
        }
        gs[grow0*9     + gcol0]     = c0;
        gs[grow0*9     + gcol0 + 1] = c1;
        gs[(grow0+8)*9 + gcol0]     = c2;
        gs[(grow0+8)*9 + gcol0 + 1] = c3;
        __syncthreads();

        // elementwise: fp32 gates + exact xp; c stays in register
        float gi = gs[uu*9      + bb] + xgi;
        float gf = gs[(32+uu)*9 + bb] + xgf;
        float gg = gs[(64+uu)*9 + bb] + xgg;
        float go = gs[(96+uu)*9 + bb] + xgo;
        c_reg = sigm(gf)*c_reg + sigm(gi)*tanh_e(gg);
        float hh = sigm(go)*tanh_e(c_reg);

        xout[((size_t)bglob*Tn + t)*HIDn + dir*Hn + u0 + uu] = hh;
        *reinterpret_cast<__nv_bfloat16*>(sm + OFF_S + bb*64 + uu*2)
            = __float2bfloat16_rn(hh);
        __syncthreads();

        // distribute my 32-unit h slice to all 8 CTAs' next-phase buffer
        {
            int rr = tid >> 5;                // destination rank
            int j  = tid & 31;                // 16B chunk id
            int sb2 = j >> 2;                 // batch
            int gq  = j & 3;                  // 16B group within 64B row
            u64 v0 = *reinterpret_cast<const u64*>(sm + OFF_S + sb2*64 + gq*16);
            u64 v1 = *reinterpret_cast<const u64*>(sm + OFF_S + sb2*64 + gq*16 + 8);
            uint32_t la = smb + OFF_H + (uint32_t)(p^1)*HPH
                        + sb2*(HSTR*2) + (u0<<1) + (gq<<4);
            uint32_t ra;
            asm volatile("mapa.shared::cluster.u32 %0, %1, %2;"
                         : "=r"(ra) : "r"(la), "r"(rr));
            asm volatile("st.shared::cluster.b64 [%0], %1;" :: "r"(ra),   "l"(v0));
            asm volatile("st.shared::cluster.b64 [%0], %1;" :: "r"(ra+8), "l"(v1));
        }

        asm volatile("barrier.cluster.arrive.aligned;" ::: "memory");
        asm volatile("barrier.cluster.wait.aligned;"   ::: "memory");
    }
}

// ---------------------------------------------------------------------------
// Logits: logits[bt][l] = x[bt][:] . cls_w[l][:] + cls_b[l]   (warp per row)
// ---------------------------------------------------------------------------
__global__ __launch_bounds__(256)
void logits_kernel(const float* __restrict__ cls_w, const float* __restrict__ cls_b){
    int row  = (blockIdx.x << 3) + (threadIdx.x >> 5);
    int lane = threadIdx.x & 31;
    const float* xr = g_xA + (size_t)row*HIDn + lane*16;
    float xv[16];
    #pragma unroll
    for (int q=0;q<4;q++){
        float4 v = *reinterpret_cast<const float4*>(xr + q*4);
        xv[q*4+0]=v.x; xv[q*4+1]=v.y; xv[q*4+2]=v.z; xv[q*4+3]=v.w;
    }
    float myout = 0.f;
    #pragma unroll
    for (int l=0;l<NLn;l++){
        const float* wr = cls_w + l*HIDn + lane*16;
        float p = 0.f;
        #pragma unroll
        for (int j=0;j<16;j++) p = fmaf(xv[j], __ldg(wr+j), p);
        #pragma unroll
        for (int o=16;o;o>>=1) p += __shfl_xor_sync(0xffffffffu, p, o);
        if (lane == l) myout = p + cls_b[l];
    }
    if (lane < NLn) g_logits[(size_t)row*NLn + lane] = myout;
}

// ---------------------------------------------------------------------------
// CRF: one warp per batch element. lanes 0..8 hold states.
// ---------------------------------------------------------------------------
__global__ void crf_kernel(const int* __restrict__ labels,
                           const float* __restrict__ start_trans,
                           const float* __restrict__ end_trans,
                           const float* __restrict__ trans){
    int b    = blockIdx.x;
    int lane = threadIdx.x;
    __shared__ float tr_s[NLn*NLn];
    for (int i = lane; i < NLn*NLn; i += 32) tr_s[i] = trans[i];
    __syncwarp();

    bool act = lane < NLn;
    float tr[NLn];
    #pragma unroll
    for (int k=0;k<NLn;k++) tr[k] = act ? trans[k*NLn + lane] : 0.f;

    const float* lg = g_logits + (size_t)b*Tn*NLn;
    const int*   lb = labels   + (size_t)b*Tn;

    float em    = act ? lg[lane] : -1e30f;
    float alpha = act ? (start_trans[lane] + em) : -1e30f;
    int prev = lb[0];
    float num = __shfl_sync(0xffffffffu, em, prev) + start_trans[prev];

    for (int t=1;t<Tn;t++){
        em = act ? lg[t*NLn + lane] : -1e30f;
        int tag = lb[t];
        float v[NLn], m = -1e30f;
        #pragma unroll
        for (int k=0;k<NLn;k++){
            float ak = __shfl_sync(0xffffffffu, alpha, k);
            v[k] = ak + tr[k];
            m = fmaxf(m, v[k]);
        }
        float s = 0.f;
        #pragma unroll
        for (int k=0;k<NLn;k++) s += __expf(v[k]-m);
        float na = m + __logf(s) + em;
        num += tr_s[prev*NLn + tag] + __shfl_sync(0xffffffffu, em, tag);
        alpha = act ? na : -1e30f;
        prev = tag;
    }
    float fa = act ? (alpha + end_trans[lane]) : -1e30f;
    float m = fa;
    #pragma unroll
    for (int o=16;o;o>>=1) m = fmaxf(m, __shfl_xor_sync(0xffffffffu, m, o));
    float s = act ? __expf(fa - m) : 0.f;
    #pragma unroll
    for (int o=16;o;o>>=1) s += __shfl_xor_sync(0xffffffffu, s, o);
    float denom = m + __logf(s);
    num += end_trans[prev];
    if (lane == 0) g_crf[b] = num - denom;
}

__global__ void finish_kernel(float* out){
    int lane = threadIdx.x;
    float s = g_crf[lane] + g_crf[lane+32];
    #pragma unroll
    for (int o=16;o;o>>=1) s += __shfl_xor_sync(0xffffffffu, s, o);
    if (lane == 0) out[0] = -s;
}

// ---------------------------------------------------------------------------
extern "C" void kernel_launch(void* const* d_in, const int* in_sizes, int n_in,
                              void* d_out, int out_size){
    const int*   ids         = (const int*)  d_in[0];
    const int*   labels      = (const int*)  d_in[1];
    const float* emb         = (const float*)d_in[2];
    const float* w_ih        = (const float*)d_in[3];
    const float* w_hh        = (const float*)d_in[4];
    const float* b_ih        = (const float*)d_in[5];
    const float* b_hh        = (const float*)d_in[6];
    const float* cls_w       = (const float*)d_in[7];
    const float* cls_b       = (const float*)d_in[8];
    const float* start_trans = (const float*)d_in[9];
    const float* end_trans   = (const float*)d_in[10];
    const float* trans       = (const float*)d_in[11];
    float* out = (float*)d_out;

    cudaFuncSetAttribute(lstm_cluster_kernel,
                         cudaFuncAttributeMaxDynamicSharedMemorySize, LSTM_SMEM);

    embed_kernel<<<BTn,128>>>(ids, emb);

    for (int layer = 0; layer < 2; ++layer){
        conv_x_kernel<<<(BTn*HIDn)/2048, 256>>>(layer);
        conv_w_kernel<<<(2048*HIDn)/2048, 256>>>(w_ih + (size_t)layer*2048*HIDn);
        gemm_xp_mma<<<dim3(16,256),256>>>(
            b_ih + (size_t)layer*2048,
            b_hh + (size_t)layer*2048);
        lstm_cluster_kernel<<<128,256,LSTM_SMEM>>>(layer,
            w_hh + (size_t)layer*2*G4n*Hn);
    }

    logits_kernel<<<BTn/8,256>>>(cls_w, cls_b);
    crf_kernel<<<Bn,32>>>(labels, start_trans, end_trans, trans);
    finish_kernel<<<1,32>>>(out);
}

// round 9
// speedup vs baseline: 3.7343x; 1.1888x over previous
#include <cuda_runtime.h>
#include <cuda_bf16.h>
#include <math.h>
#include <stdint.h>

// ---------------------------------------------------------------------------
// Problem constants
// ---------------------------------------------------------------------------
#define Bn    64
#define Tn    512
#define HIDn  512
#define Hn    256
#define G4n   1024           // 4*H
#define NLn   9
#define BTn   (Bn*Tn)        // 32768

typedef unsigned long long u64;

// ---------------------------------------------------------------------------
// Device scratch (cudaMalloc forbidden -> module globals)
// ---------------------------------------------------------------------------
__device__ float g_xA[BTn*HIDn];                  // 64 MB  (final layer output, fp32)
__device__ __nv_bfloat16 g_xh[BTn*HIDn];          // 32 MB  (bf16 GEMM A: emb / layer-0 h)
__device__ __nv_bfloat16 g_wh[2048*HIDn];         //  2 MB  (bf16 GEMM B = W_ih layer)
__device__ float g_xp[2ll*BTn*G4n];               // 256 MB [dir][bt][gate-row]
__device__ float g_logits[BTn*NLn];
__device__ float g_crf[Bn];

// ---------------------------------------------------------------------------
__device__ __forceinline__ float tanh_a(float x){
    float y; asm("tanh.approx.f32 %0, %1;" : "=f"(y) : "f"(x)); return y;
}
__device__ __forceinline__ float sigm_a(float x){
    return fmaf(0.5f, tanh_a(0.5f*x), 0.5f);
}

#define CP16(d, s) asm volatile("cp.async.cg.shared.global [%0], [%1], 16;" :: "r"(d), "l"(s))
#define CP_COMMIT() asm volatile("cp.async.commit_group;")

// ---------------------------------------------------------------------------
// Embedding gather directly to bf16: g_xh[bt][:] = bf16(emb[ids[bt]][:])
// ---------------------------------------------------------------------------
__global__ void embed_kernel(const int* __restrict__ ids,
                             const float* __restrict__ emb){
    int bt = blockIdx.x;
    int id = ids[bt];
    float4 v = reinterpret_cast<const float4*>(emb + (size_t)id * HIDn)[threadIdx.x];
    __nv_bfloat162 o0 = __floats2bfloat162_rn(v.x, v.y);
    __nv_bfloat162 o1 = __floats2bfloat162_rn(v.z, v.w);
    uint2 pk = make_uint2(*reinterpret_cast<uint32_t*>(&o0),
                          *reinterpret_cast<uint32_t*>(&o1));
    *reinterpret_cast<uint2*>(g_xh + (size_t)bt*HIDn + threadIdx.x*4) = pk;
}

// ---------------------------------------------------------------------------
// fp32 -> bf16 weight convert
// ---------------------------------------------------------------------------
__global__ __launch_bounds__(256)
void conv_w_kernel(const float* __restrict__ W){
    size_t i = (((size_t)blockIdx.x << 8) + threadIdx.x) << 3;
    float4 v0 = *reinterpret_cast<const float4*>(W + i);
    float4 v1 = *reinterpret_cast<const float4*>(W + i + 4);
    __nv_bfloat162 o[4];
    o[0] = __floats2bfloat162_rn(v0.x, v0.y);
    o[1] = __floats2bfloat162_rn(v0.z, v0.w);
    o[2] = __floats2bfloat162_rn(v1.x, v1.y);
    o[3] = __floats2bfloat162_rn(v1.z, v1.w);
    *reinterpret_cast<uint4*>(g_wh + i) = *reinterpret_cast<uint4*>(o);
}

// ---------------------------------------------------------------------------
// Input projection on tensor cores (bf16 mma.sync, fp32 accumulate):
// C(32768 x 2048) = A(32768x512) * W(2048x512)^T ; xp = C + bi + bh.
// cp.async 4-buffer pipeline (issue-ahead 2), ONE __syncthreads per k-iter.
// CTA tile 128x128x32; 8 warps 2x4; warp tile 64x32; m16n8k16.
// ---------------------------------------------------------------------------
#define ASTR 40
#define ABUF 10240                    // bytes per 128x32 bf16 buffer (stride 40)
#define GSM_TOTAL (8*ABUF)            // 4 A buffers + 4 B buffers = 81920 B

__global__ __launch_bounds__(256, 2)
void gemm_xp_mma(const float* __restrict__ bi, const float* __restrict__ bh){
    extern __shared__ __align__(16) char gsm[];
    const uint32_t smb = (uint32_t)__cvta_generic_to_shared(gsm);

    const int tid  = threadIdx.x;
    const int wid  = tid >> 5;
    const int lane = tid & 31;
    const int m0 = blockIdx.y << 7;
    const int n0 = blockIdx.x << 7;
    const int wm = wid >> 2;
    const int wn = wid & 3;

    float acc[4][4][4];
    #pragma unroll
    for (int mi=0;mi<4;mi++)
        #pragma unroll
        for (int ni=0;ni<4;ni++)
            #pragma unroll
            for (int r=0;r<4;r++) acc[mi][ni][r]=0.f;

    // G->S: thread covers 32B (16 bf16) of one row per stage
    const int lrow = tid >> 1;
    const int lqo  = (tid & 1) << 4;
    const __nv_bfloat16* gA = g_xh + (size_t)(m0 + lrow)*HIDn + lqo;
    const __nv_bfloat16* gB = g_wh + (size_t)(n0 + lrow)*HIDn + lqo;
    const uint32_t rowb = lrow*(ASTR*2) + lqo*2;     // byte offset inside a buffer

    // ldmatrix byte offsets inside a buffer
    uint32_t aRel[4], bRel[4];
    {
        int r16 = lane & 15;
        #pragma unroll
        for (int mi=0;mi<4;mi++)
            aRel[mi] = (((wm<<6) + (mi<<4) + r16)*ASTR + ((lane>>4) << 3)) * 2;
        #pragma unroll
        for (int ni=0;ni<4;ni++)
            bRel[ni] = (((wn<<5) + (ni<<3) + (r16 & 7))*ASTR + (((r16>>3)&1) << 3)) * 2;
    }

    // pipeline prologue: stages 0,1
    #pragma unroll
    for (int s = 0; s < 2; ++s){
        uint32_t da = smb + (s&3)*ABUF + rowb;
        uint32_t db = smb + 4*ABUF + (s&3)*ABUF + rowb;
        const __nv_bfloat16* sa = gA + s*32;
        const __nv_bfloat16* sb = gB + s*32;
        CP16(da, sa); CP16(da+16, sa+8);
        CP16(db, sb); CP16(db+16, sb+8);
        CP_COMMIT();
    }

    for (int it = 0; it < 16; ++it){
        if (it < 14){
            int s = it + 2;
            uint32_t da = smb + (s&3)*ABUF + rowb;
            uint32_t db = smb + 4*ABUF + (s&3)*ABUF + rowb;
            const __nv_bfloat16* sa = gA + s*32;
            const __nv_bfloat16* sb = gB + s*32;
            CP16(da, sa); CP16(da+16, sa+8);
            CP16(db, sb); CP16(db+16, sb+8);
            CP_COMMIT();
            asm volatile("cp.async.wait_group 2;");
        } else {
            asm volatile("cp.async.wait_group 0;");
        }
        __syncthreads();

        const uint32_t aBase = smb + (it&3)*ABUF;
        const uint32_t bBase = smb + 4*ABUF + (it&3)*ABUF;
        #pragma unroll
        for (int kk = 0; kk < 2; ++kk){
            uint32_t af[4][4];
            #pragma unroll
            for (int mi=0;mi<4;mi++){
                asm volatile("ldmatrix.sync.aligned.m8n8.x4.shared.b16 "
                    "{%0,%1,%2,%3}, [%4];"
                    : "=r"(af[mi][0]),"=r"(af[mi][1]),"=r"(af[mi][2]),"=r"(af[mi][3])
                    : "r"(aBase + aRel[mi] + kk*32));
            }
            uint32_t bfr[4][2];
            #pragma unroll
            for (int ni=0;ni<4;ni++){
                asm volatile("ldmatrix.sync.aligned.m8n8.x2.shared.b16 "
                    "{%0,%1}, [%2];"
                    : "=r"(bfr[ni][0]),"=r"(bfr[ni][1])
                    : "r"(bBase + bRel[ni] + kk*32));
            }
            #pragma unroll
            for (int mi=0;mi<4;mi++){
                #pragma unroll
                for (int ni=0;ni<4;ni++){
                    asm volatile(
                        "mma.sync.aligned.m16n8k16.row.col.f32.bf16.bf16.f32 "
                        "{%0,%1,%2,%3}, {%4,%5,%6,%7}, {%8,%9}, {%0,%1,%2,%3};"
                        : "+f"(acc[mi][ni][0]),"+f"(acc[mi][ni][1]),
                          "+f"(acc[mi][ni][2]),"+f"(acc[mi][ni][3])
                        : "r"(af[mi][0]),"r"(af[mi][1]),"r"(af[mi][2]),"r"(af[mi][3]),
                          "r"(bfr[ni][0]),"r"(bfr[ni][1]));
                }
            }
        }
    }

    const int dir = n0 >> 10;
    #pragma unroll
    for (int ni=0;ni<4;ni++){
        int ncol = n0 + (wn<<5) + (ni<<3) + ((lane & 3) << 1);
        float bs0 = bi[ncol]   + bh[ncol];
        float bs1 = bi[ncol+1] + bh[ncol+1];
        int g = ncol & 1023;
        #pragma unroll
        for (int mi=0;mi<4;mi++){
            int mrow = m0 + (wm<<6) + (mi<<4) + (lane >> 2);
            float2 v0 = make_float2(acc[mi][ni][0] + bs0, acc[mi][ni][1] + bs1);
            float2 v1 = make_float2(acc[mi][ni][2] + bs0, acc[mi][ni][3] + bs1);
            *reinterpret_cast<float2*>(&g_xp[((size_t)dir*BTn + mrow)*G4n + g])   = v0;
            *reinterpret_cast<float2*>(&g_xp[((size_t)dir*BTn + mrow+8)*G4n + g]) = v1;
        }
    }
}

// ---------------------------------------------------------------------------
// Cluster-based persistent bidirectional LSTM (as R7, elementwise on
// tanh.approx; layer 0 emits bf16 to g_xh, layer 1 fp32 to g_xA).
// Smem: WSTG[128][264]bf16 @0 | HBUF[2][8][264]bf16 @67584 | GS[128][9]f32
// @76032 | STAGE[8][32]bf16 @80640
// ---------------------------------------------------------------------------
#define HSTR 264
#define OFF_W 0
#define OFF_H 67584
#define OFF_G 76032
#define OFF_S 80640
#define LSTM_SMEM 81152
#define HPH 4224

__global__ __launch_bounds__(256, 1) __cluster_dims__(8, 1, 1)
void lstm_cluster_kernel(int layer, const float* __restrict__ whh){
    extern __shared__ __align__(16) char sm[];

    const int tid  = threadIdx.x;
    const int wid  = tid >> 5;
    const int lane = tid & 31;
    const int rank = blockIdx.x & 7;
    const int cid  = blockIdx.x >> 3;
    const int dir  = cid & 1;
    const int bgrp = cid >> 1;
    const int u0   = rank << 5;

    const uint32_t smb = (uint32_t)__cvta_generic_to_shared(sm);

    // stage W_hh (fp32->bf16) into smem: row r = gate*32+uu
    for (int idx = tid; idx < 128*64; idx += 256){
        int r  = idx >> 6;
        int kq = (idx & 63) << 2;
        int grow = dir*G4n + (r>>5)*Hn + u0 + (r&31);
        float4 v = *reinterpret_cast<const float4*>(whh + (size_t)grow*Hn + kq);
        __nv_bfloat162 o0 = __floats2bfloat162_rn(v.x, v.y);
        __nv_bfloat162 o1 = __floats2bfloat162_rn(v.z, v.w);
        uint2 pk = make_uint2(*reinterpret_cast<uint32_t*>(&o0),
                              *reinterpret_cast<uint32_t*>(&o1));
        *reinterpret_cast<uint2*>(sm + OFF_W + r*(HSTR*2) + kq*2) = pk;
    }
    for (int i = tid; i < 2*8*HSTR; i += 256)
        *reinterpret_cast<__nv_bfloat16*>(sm + OFF_H + i*2) = __nv_bfloat16(0.f);
    __syncthreads();

    // preload W fragments into registers: warp w -> gate rows 16w..16w+15
    uint32_t afr[16][4];
    {
        uint32_t aAddr = smb + OFF_W + (wid*16 + (lane & 15))*(HSTR*2)
                       + (((lane >> 4) << 3) << 1);
        #pragma unroll
        for (int kk = 0; kk < 16; ++kk){
            asm volatile("ldmatrix.sync.aligned.m8n8.x4.shared.b16 "
                "{%0,%1,%2,%3}, [%4];"
                : "=r"(afr[kk][0]),"=r"(afr[kk][1]),"=r"(afr[kk][2]),"=r"(afr[kk][3])
                : "r"(aAddr + kk*32));
        }
    }

    const int r16 = lane & 15;
    const uint32_t bBase = smb + OFF_H + (r16 & 7)*(HSTR*2) + (((r16>>3)&1) << 4);

    const int bb = tid >> 5;
    const int uu = tid & 31;
    const int bglob = (bgrp << 3) + bb;
    float c_reg = 0.f;

    float* gs = reinterpret_cast<float*>(sm + OFF_G);
    const int grow0 = wid*16 + (lane >> 2);
    const int gcol0 = (lane & 3) << 1;

    asm volatile("barrier.cluster.arrive.aligned;" ::: "memory");
    asm volatile("barrier.cluster.wait.aligned;"   ::: "memory");

    for (int step = 0; step < Tn; ++step){
        const int t = dir ? (Tn-1-step) : step;
        const int p = step & 1;

        const float* xpb = g_xp + ((size_t)dir*BTn + (size_t)bglob*Tn + t)*G4n + u0 + uu;
        float xgi = __ldcs(xpb);
        float xgf = __ldcs(xpb + 256);
        float xgg = __ldcs(xpb + 512);
        float xgo = __ldcs(xpb + 768);

        // gates[16 rows x 8 batches] = W(regs) @ h(smem)
        float c0=0.f, c1=0.f, c2=0.f, c3=0.f;
        {
            const uint32_t bA = bBase + (uint32_t)p*HPH;
            #pragma unroll
            for (int kk = 0; kk < 16; ++kk){
                uint32_t b0, b1;
                asm volatile("ldmatrix.sync.aligned.m8n8.x2.shared.b16 "
                    "{%0,%1}, [%2];" : "=r"(b0),"=r"(b1) : "r"(bA + kk*32));
                asm volatile(
                    "mma.sync.aligned.m16n8k16.row.col.f32.bf16.bf16.f32 "
                    "{%0,%1,%2,%3}, {%4,%5,%6,%7}, {%8,%9}, {%0,%1,%2,%3};"
                    : "+f"(c0),"+f"(c1),"+f"(c2),"+f"(c3)
                    : "r"(afr[kk][0]),"r"(afr[kk][1]),"r"(afr[kk][2]),"r"(afr[kk][3]),
                      "r"(b0),"r"(b1));
            }
        }
        gs[grow0*9     + gcol0]     = c0;
        gs[grow0*9     + gcol0 + 1] = c1;
        gs[(grow0+8)*9 + gcol0]     = c2;
        gs[(grow0+8)*9 + gcol0 + 1] = c3;
        __syncthreads();

        // elementwise (tanh.approx activations; c stays in register)
        float gi = gs[uu*9      + bb] + xgi;
        float gf = gs[(32+uu)*9 + bb] + xgf;
        float gg = gs[(64+uu)*9 + bb] + xgg;
        float go = gs[(96+uu)*9 + bb] + xgo;
        c_reg = sigm_a(gf)*c_reg + sigm_a(gi)*tanh_a(gg);
        float hh = sigm_a(go)*tanh_a(c_reg);

        *reinterpret_cast<__nv_bfloat16*>(sm + OFF_S + bb*64 + uu*2)
            = __float2bfloat16_rn(hh);
        __syncthreads();

        // distribute my 32-unit h slice to all 8 CTAs' next-phase buffer
        {
            int rr = tid >> 5;
            int j  = tid & 31;
            int sb2 = j >> 2;
            int gq  = j & 3;
            u64 v0 = *reinterpret_cast<const u64*>(sm + OFF_S + sb2*64 + gq*16);
            u64 v1 = *reinterpret_cast<const u64*>(sm + OFF_S + sb2*64 + gq*16 + 8);
            uint32_t la = smb + OFF_H + (uint32_t)(p^1)*HPH
                        + sb2*(HSTR*2) + (u0<<1) + (gq<<4);
            uint32_t ra;
            asm volatile("mapa.shared::cluster.u32 %0, %1, %2;"
                         : "=r"(ra) : "r"(la), "r"(rr));
            asm volatile("st.shared::cluster.b64 [%0], %1;" :: "r"(ra),   "l"(v0));
            asm volatile("st.shared::cluster.b64 [%0], %1;" :: "r"(ra+8), "l"(v1));
        }

        asm volatile("barrier.cluster.arrive.aligned;" ::: "memory");

        // global h output store overlaps the barrier wait
        if (layer == 0){
            g_xh[((size_t)bglob*Tn + t)*HIDn + dir*Hn + u0 + uu]
                = __float2bfloat16_rn(hh);
        } else {
            g_xA[((size_t)bglob*Tn + t)*HIDn + dir*Hn + u0 + uu] = hh;
        }

        asm volatile("barrier.cluster.wait.aligned;" ::: "memory");
    }
}

// ---------------------------------------------------------------------------
// Logits: logits[bt][l] = x[bt][:] . cls_w[l][:] + cls_b[l]   (warp per row)
// ---------------------------------------------------------------------------
__global__ __launch_bounds__(256)
void logits_kernel(const float* __restrict__ cls_w, const float* __restrict__ cls_b){
    int row  = (blockIdx.x << 3) + (threadIdx.x >> 5);
    int lane = threadIdx.x & 31;
    const float* xr = g_xA + (size_t)row*HIDn + lane*16;
    float xv[16];
    #pragma unroll
    for (int q=0;q<4;q++){
        float4 v = *reinterpret_cast<const float4*>(xr + q*4);
        xv[q*4+0]=v.x; xv[q*4+1]=v.y; xv[q*4+2]=v.z; xv[q*4+3]=v.w;
    }
    float myout = 0.f;
    #pragma unroll
    for (int l=0;l<NLn;l++){
        const float* wr = cls_w + l*HIDn + lane*16;
        float p = 0.f;
        #pragma unroll
        for (int j=0;j<16;j++) p = fmaf(xv[j], __ldg(wr+j), p);
        #pragma unroll
        for (int o=16;o;o>>=1) p += __shfl_xor_sync(0xffffffffu, p, o);
        if (lane == l) myout = p + cls_b[l];
    }
    if (lane < NLn) g_logits[(size_t)row*NLn + lane] = myout;
}

// ---------------------------------------------------------------------------
// CRF: one warp per batch element. lanes 0..8 hold states.
// ---------------------------------------------------------------------------
__global__ void crf_kernel(const int* __restrict__ labels,
                           const float* __restrict__ start_trans,
                           const float* __restrict__ end_trans,
                           const float* __restrict__ trans){
    int b    = blockIdx.x;
    int lane = threadIdx.x;
    __shared__ float tr_s[NLn*NLn];
    for (int i = lane; i < NLn*NLn; i += 32) tr_s[i] = trans[i];
    __syncwarp();

    bool act = lane < NLn;
    float tr[NLn];
    #pragma unroll
    for (int k=0;k<NLn;k++) tr[k] = act ? trans[k*NLn + lane] : 0.f;

    const float* lg = g_logits + (size_t)b*Tn*NLn;
    const int*   lb = labels   + (size_t)b*Tn;

    float em    = act ? lg[lane] : -1e30f;
    float alpha = act ? (start_trans[lane] + em) : -1e30f;
    int prev = lb[0];
    float num = __shfl_sync(0xffffffffu, em, prev) + start_trans[prev];

    for (int t=1;t<Tn;t++){
        em = act ? lg[t*NLn + lane] : -1e30f;
        int tag = lb[t];
        float v[NLn], m = -1e30f;
        #pragma unroll
        for (int k=0;k<NLn;k++){
            float ak = __shfl_sync(0xffffffffu, alpha, k);
            v[k] = ak + tr[k];
            m = fmaxf(m, v[k]);
        }
        float s = 0.f;
        #pragma unroll
        for (int k=0;k<NLn;k++) s += __expf(v[k]-m);
        float na = m + __logf(s) + em;
        num += tr_s[prev*NLn + tag] + __shfl_sync(0xffffffffu, em, tag);
        alpha = act ? na : -1e30f;
        prev = tag;
    }
    float fa = act ? (alpha + end_trans[lane]) : -1e30f;
    float m = fa;
    #pragma unroll
    for (int o=16;o;o>>=1) m = fmaxf(m, __shfl_xor_sync(0xffffffffu, m, o));
    float s = act ? __expf(fa - m) : 0.f;
    #pragma unroll
    for (int o=16;o;o>>=1) s += __shfl_xor_sync(0xffffffffu, s, o);
    float denom = m + __logf(s);
    num += end_trans[prev];
    if (lane == 0) g_crf[b] = num - denom;
}

__global__ void finish_kernel(float* out){
    int lane = threadIdx.x;
    float s = g_crf[lane] + g_crf[lane+32];
    #pragma unroll
    for (int o=16;o;o>>=1) s += __shfl_xor_sync(0xffffffffu, s, o);
    if (lane == 0) out[0] = -s;
}

// ---------------------------------------------------------------------------
extern "C" void kernel_launch(void* const* d_in, const int* in_sizes, int n_in,
                              void* d_out, int out_size){
    const int*   ids         = (const int*)  d_in[0];
    const int*   labels      = (const int*)  d_in[1];
    const float* emb         = (const float*)d_in[2];
    const float* w_ih        = (const float*)d_in[3];
    const float* w_hh        = (const float*)d_in[4];
    const float* b_ih        = (const float*)d_in[5];
    const float* b_hh        = (const float*)d_in[6];
    const float* cls_w       = (const float*)d_in[7];
    const float* cls_b       = (const float*)d_in[8];
    const float* start_trans = (const float*)d_in[9];
    const float* end_trans   = (const float*)d_in[10];
    const float* trans       = (const float*)d_in[11];
    float* out = (float*)d_out;

    cudaFuncSetAttribute(lstm_cluster_kernel,
                         cudaFuncAttributeMaxDynamicSharedMemorySize, LSTM_SMEM);
    cudaFuncSetAttribute(gemm_xp_mma,
                         cudaFuncAttributeMaxDynamicSharedMemorySize, GSM_TOTAL);

    embed_kernel<<<BTn,128>>>(ids, emb);

    for (int layer = 0; layer < 2; ++layer){
        conv_w_kernel<<<(2048*HIDn)/2048, 256>>>(w_ih + (size_t)layer*2048*HIDn);
        gemm_xp_mma<<<dim3(16,256),256,GSM_TOTAL>>>(
            b_ih + (size_t)layer*2048,
            b_hh + (size_t)layer*2048);
        lstm_cluster_kernel<<<128,256,LSTM_SMEM>>>(layer,
            w_hh + (size_t)layer*2*G4n*Hn);
    }

    logits_kernel<<<BTn/8,256>>>(cls_w, cls_b);
    crf_kernel<<<Bn,32>>>(labels, start_trans, end_trans, trans);
    finish_kernel<<<1,32>>>(out);
}

// round 11
// speedup vs baseline: 4.1517x; 1.1118x over previous
#include <cuda_runtime.h>
#include <cuda_bf16.h>
#include <math.h>
#include <stdint.h>

// ---------------------------------------------------------------------------
// Problem constants
// ---------------------------------------------------------------------------
#define Bn    64
#define Tn    512
#define HIDn  512
#define Hn    256
#define G4n   1024           // 4*H
#define NLn   9
#define BTn   (Bn*Tn)        // 32768

typedef unsigned long long u64;

// ---------------------------------------------------------------------------
// Device scratch (cudaMalloc forbidden -> module globals)
// ---------------------------------------------------------------------------
__device__ float g_xA[BTn*HIDn];                  // 64 MB  (final layer output, fp32)
__device__ __nv_bfloat16 g_xh[BTn*HIDn];          // 32 MB  (bf16 GEMM A: emb / layer-0 h)
__device__ __nv_bfloat16 g_wh[2048*HIDn];         //  2 MB  (bf16 GEMM B = W_ih layer)
__device__ float g_xp[2ll*BTn*G4n];               // 256 MB [dir][bt][gate-row]
__device__ float g_logits[BTn*NLn];
__device__ float g_crf[Bn];

// ---------------------------------------------------------------------------
__device__ __forceinline__ float tanh_a(float x){
    float y; asm("tanh.approx.f32 %0, %1;" : "=f"(y) : "f"(x)); return y;
}
__device__ __forceinline__ float sigm_a(float x){
    return fmaf(0.5f, tanh_a(0.5f*x), 0.5f);
}

#define CP16(d, s) asm volatile("cp.async.cg.shared.global [%0], [%1], 16;" :: "r"(d), "l"(s))
#define CP_COMMIT() asm volatile("cp.async.commit_group;")

// ---------------------------------------------------------------------------
// Embedding gather directly to bf16: g_xh[bt][:] = bf16(emb[ids[bt]][:])
// ---------------------------------------------------------------------------
__global__ void embed_kernel(const int* __restrict__ ids,
                             const float* __restrict__ emb){
    int bt = blockIdx.x;
    int id = ids[bt];
    float4 v = reinterpret_cast<const float4*>(emb + (size_t)id * HIDn)[threadIdx.x];
    __nv_bfloat162 o0 = __floats2bfloat162_rn(v.x, v.y);
    __nv_bfloat162 o1 = __floats2bfloat162_rn(v.z, v.w);
    uint2 pk = make_uint2(*reinterpret_cast<uint32_t*>(&o0),
                          *reinterpret_cast<uint32_t*>(&o1));
    *reinterpret_cast<uint2*>(g_xh + (size_t)bt*HIDn + threadIdx.x*4) = pk;
}

// ---------------------------------------------------------------------------
// fp32 -> bf16 weight convert
// ---------------------------------------------------------------------------
__global__ __launch_bounds__(256)
void conv_w_kernel(const float* __restrict__ W){
    size_t i = (((size_t)blockIdx.x << 8) + threadIdx.x) << 3;
    float4 v0 = *reinterpret_cast<const float4*>(W + i);
    float4 v1 = *reinterpret_cast<const float4*>(W + i + 4);
    __nv_bfloat162 o[4];
    o[0] = __floats2bfloat162_rn(v0.x, v0.y);
    o[1] = __floats2bfloat162_rn(v0.z, v0.w);
    o[2] = __floats2bfloat162_rn(v1.x, v1.y);
    o[3] = __floats2bfloat162_rn(v1.z, v1.w);
    *reinterpret_cast<uint4*>(g_wh + i) = *reinterpret_cast<uint4*>(o);
}

// ---------------------------------------------------------------------------
// Input projection on tensor cores (bf16 mma.sync, fp32 accumulate):
// C(32768 x 2048) = A(32768x512) * W(2048x512)^T ; xp = C + bi + bh.
// cp.async 4-buffer pipeline (issue-ahead 2), ONE __syncthreads per k-iter.
// (unchanged from R8)
// ---------------------------------------------------------------------------
#define ASTR 40
#define ABUF 10240
#define GSM_TOTAL (8*ABUF)

__global__ __launch_bounds__(256, 2)
void gemm_xp_mma(const float* __restrict__ bi, const float* __restrict__ bh){
    extern __shared__ __align__(16) char gsm[];
    const uint32_t smb = (uint32_t)__cvta_generic_to_shared(gsm);

    const int tid  = threadIdx.x;
    const int wid  = tid >> 5;
    const int lane = tid & 31;
    const int m0 = blockIdx.y << 7;
    const int n0 = blockIdx.x << 7;
    const int wm = wid >> 2;
    const int wn = wid & 3;

    float acc[4][4][4];
    #pragma unroll
    for (int mi=0;mi<4;mi++)
        #pragma unroll
        for (int ni=0;ni<4;ni++)
            #pragma unroll
            for (int r=0;r<4;r++) acc[mi][ni][r]=0.f;

    const int lrow = tid >> 1;
    const int lqo  = (tid & 1) << 4;
    const __nv_bfloat16* gA = g_xh + (size_t)(m0 + lrow)*HIDn + lqo;
    const __nv_bfloat16* gB = g_wh + (size_t)(n0 + lrow)*HIDn + lqo;
    const uint32_t rowb = lrow*(ASTR*2) + lqo*2;

    uint32_t aRel[4], bRel[4];
    {
        int r16 = lane & 15;
        #pragma unroll
        for (int mi=0;mi<4;mi++)
            aRel[mi] = (((wm<<6) + (mi<<4) + r16)*ASTR + ((lane>>4) << 3)) * 2;
        #pragma unroll
        for (int ni=0;ni<4;ni++)
            bRel[ni] = (((wn<<5) + (ni<<3) + (r16 & 7))*ASTR + (((r16>>3)&1) << 3)) * 2;
    }

    #pragma unroll
    for (int s = 0; s < 2; ++s){
        uint32_t da = smb + (s&3)*ABUF + rowb;
        uint32_t db = smb + 4*ABUF + (s&3)*ABUF + rowb;
        const __nv_bfloat16* sa = gA + s*32;
        const __nv_bfloat16* sb = gB + s*32;
        CP16(da, sa); CP16(da+16, sa+8);
        CP16(db, sb); CP16(db+16, sb+8);
        CP_COMMIT();
    }

    for (int it = 0; it < 16; ++it){
        if (it < 14){
            int s = it + 2;
            uint32_t da = smb + (s&3)*ABUF + rowb;
            uint32_t db = smb + 4*ABUF + (s&3)*ABUF + rowb;
            const __nv_bfloat16* sa = gA + s*32;
            const __nv_bfloat16* sb = gB + s*32;
            CP16(da, sa); CP16(da+16, sa+8);
            CP16(db, sb); CP16(db+16, sb+8);
            CP_COMMIT();
            asm volatile("cp.async.wait_group 2;");
        } else {
            asm volatile("cp.async.wait_group 0;");
        }
        __syncthreads();

        const uint32_t aBase = smb + (it&3)*ABUF;
        const uint32_t bBase = smb + 4*ABUF + (it&3)*ABUF;
        #pragma unroll
        for (int kk = 0; kk < 2; ++kk){
            uint32_t af[4][4];
            #pragma unroll
            for (int mi=0;mi<4;mi++){
                asm volatile("ldmatrix.sync.aligned.m8n8.x4.shared.b16 "
                    "{%0,%1,%2,%3}, [%4];"
                    : "=r"(af[mi][0]),"=r"(af[mi][1]),"=r"(af[mi][2]),"=r"(af[mi][3])
                    : "r"(aBase + aRel[mi] + kk*32));
            }
            uint32_t bfr[4][2];
            #pragma unroll
            for (int ni=0;ni<4;ni++){
                asm volatile("ldmatrix.sync.aligned.m8n8.x2.shared.b16 "
                    "{%0,%1}, [%2];"
                    : "=r"(bfr[ni][0]),"=r"(bfr[ni][1])
                    : "r"(bBase + bRel[ni] + kk*32));
            }
            #pragma unroll
            for (int mi=0;mi<4;mi++){
                #pragma unroll
                for (int ni=0;ni<4;ni++){
                    asm volatile(
                        "mma.sync.aligned.m16n8k16.row.col.f32.bf16.bf16.f32 "
                        "{%0,%1,%2,%3}, {%4,%5,%6,%7}, {%8,%9}, {%0,%1,%2,%3};"
                        : "+f"(acc[mi][ni][0]),"+f"(acc[mi][ni][1]),
                          "+f"(acc[mi][ni][2]),"+f"(acc[mi][ni][3])
                        : "r"(af[mi][0]),"r"(af[mi][1]),"r"(af[mi][2]),"r"(af[mi][3]),
                          "r"(bfr[ni][0]),"r"(bfr[ni][1]));
                }
            }
        }
    }

    const int dir = n0 >> 10;
    #pragma unroll
    for (int ni=0;ni<4;ni++){
        int ncol = n0 + (wn<<5) + (ni<<3) + ((lane & 3) << 1);
        float bs0 = bi[ncol]   + bh[ncol];
        float bs1 = bi[ncol+1] + bh[ncol+1];
        int g = ncol & 1023;
        #pragma unroll
        for (int mi=0;mi<4;mi++){
            int mrow = m0 + (wm<<6) + (mi<<4) + (lane >> 2);
            float2 v0 = make_float2(acc[mi][ni][0] + bs0, acc[mi][ni][1] + bs1);
            float2 v1 = make_float2(acc[mi][ni][2] + bs0, acc[mi][ni][3] + bs1);
            *reinterpret_cast<float2*>(&g_xp[((size_t)dir*BTn + mrow)*G4n + g])   = v0;
            *reinterpret_cast<float2*>(&g_xp[((size_t)dir*BTn + mrow+8)*G4n + g]) = v1;
        }
    }
}

// ---------------------------------------------------------------------------
// Cluster-based persistent bidirectional LSTM.
// R9: xp prefetched one step ahead (registers), 4-way mma accumulator chains,
// cluster barrier replaced by 2-phase mbarrier (release/acquire cluster scope).
// Smem: WSTG[128][264]bf16 @0 | HBUF[2][8][264]bf16 @67584 | GS[128][9]f32
// @76032 | STAGE[8][32]bf16 @80640 | MB[2] @81152
// ---------------------------------------------------------------------------
#define HSTR 264
#define OFF_W 0
#define OFF_H 67584
#define OFF_G 76032
#define OFF_S 80640
#define OFF_MB 81152
#define LSTM_SMEM 81280
#define HPH 4224

__global__ __launch_bounds__(256, 1) __cluster_dims__(8, 1, 1)
void lstm_cluster_kernel(int layer, const float* __restrict__ whh){
    extern __shared__ __align__(16) char sm[];

    const int tid  = threadIdx.x;
    const int wid  = tid >> 5;
    const int lane = tid & 31;
    const int rank = blockIdx.x & 7;
    const int cid  = blockIdx.x >> 3;
    const int dir  = cid & 1;
    const int bgrp = cid >> 1;
    const int u0   = rank << 5;

    const uint32_t smb = (uint32_t)__cvta_generic_to_shared(sm);

    // stage W_hh (fp32->bf16) into smem: row r = gate*32+uu
    for (int idx = tid; idx < 128*64; idx += 256){
        int r  = idx >> 6;
        int kq = (idx & 63) << 2;
        int grow = dir*G4n + (r>>5)*Hn + u0 + (r&31);
        float4 v = *reinterpret_cast<const float4*>(whh + (size_t)grow*Hn + kq);
        __nv_bfloat162 o0 = __floats2bfloat162_rn(v.x, v.y);
        __nv_bfloat162 o1 = __floats2bfloat162_rn(v.z, v.w);
        uint2 pk = make_uint2(*reinterpret_cast<uint32_t*>(&o0),
                              *reinterpret_cast<uint32_t*>(&o1));
        *reinterpret_cast<uint2*>(sm + OFF_W + r*(HSTR*2) + kq*2) = pk;
    }
    for (int i = tid; i < 2*8*HSTR; i += 256)
        *reinterpret_cast<__nv_bfloat16*>(sm + OFF_H + i*2) = __nv_bfloat16(0.f);

    // init the two step mbarriers (count = 8 arrivals, one per cluster CTA)
    if (tid == 0){
        asm volatile("mbarrier.init.shared.b64 [%0], %1;" :: "r"(smb+OFF_MB),   "r"(8) : "memory");
        asm volatile("mbarrier.init.shared.b64 [%0], %1;" :: "r"(smb+OFF_MB+8), "r"(8) : "memory");
    }
    __syncthreads();

    // preload W fragments into registers: warp w -> gate rows 16w..16w+15
    uint32_t afr[16][4];
    {
        uint32_t aAddr = smb + OFF_W + (wid*16 + (lane & 15))*(HSTR*2)
                       + (((lane >> 4) << 3) << 1);
        #pragma unroll
        for (int kk = 0; kk < 16; ++kk){
            asm volatile("ldmatrix.sync.aligned.m8n8.x4.shared.b16 "
                "{%0,%1,%2,%3}, [%4];"
                : "=r"(afr[kk][0]),"=r"(afr[kk][1]),"=r"(afr[kk][2]),"=r"(afr[kk][3])
                : "r"(aAddr + kk*32));
        }
    }

    const int r16 = lane & 15;
    const uint32_t bBase = smb + OFF_H + (r16 & 7)*(HSTR*2) + (((r16>>3)&1) << 4);

    const int bb = tid >> 5;
    const int uu = tid & 31;
    const int bglob = (bgrp << 3) + bb;
    float c_reg = 0.f;

    float* gs = reinterpret_cast<float*>(sm + OFF_G);
    const int grow0 = wid*16 + (lane >> 2);
    const int gcol0 = (lane & 3) << 1;

    // h zero + mbarrier init visible cluster-wide before any remote traffic
    asm volatile("barrier.cluster.arrive.aligned;" ::: "memory");
    asm volatile("barrier.cluster.wait.aligned;"   ::: "memory");

    // xp prefetch for step 0
    const float* xp0 = g_xp + ((size_t)dir*BTn + (size_t)bglob*Tn)*G4n + u0 + uu;
    float xgi, xgf, xgg, xgo;
    {
        const float* x = xp0 + (size_t)(dir ? (Tn-1) : 0)*G4n;
        xgi = __ldcs(x); xgf = __ldcs(x+256); xgg = __ldcs(x+512); xgo = __ldcs(x+768);
    }

    int ph0 = 0, ph1 = 0;        // per-mbarrier phase parity

    for (int step = 0; step < Tn; ++step){
        const int t = dir ? (Tn-1-step) : step;
        const int p = step & 1;
        const int q = p ^ 1;

        // prefetch next step's xp (consumed next iteration -> fully hidden)
        float ngi=0.f, ngf=0.f, ngg=0.f, ngo=0.f;
        if (step+1 < Tn){
            const float* x = xp0 + (size_t)(dir ? (Tn-2-step) : (step+1))*G4n;
            ngi = __ldcs(x); ngf = __ldcs(x+256); ngg = __ldcs(x+512); ngo = __ldcs(x+768);
        }

        // gates = W(regs) @ h(smem) : 4 independent accumulator chains
        float d[4][4];
        #pragma unroll
        for (int j=0;j<4;j++){ d[j][0]=0.f; d[j][1]=0.f; d[j][2]=0.f; d[j][3]=0.f; }
        {
            const uint32_t bA = bBase + (uint32_t)p*HPH;
            #pragma unroll
            for (int kk = 0; kk < 16; ++kk){
                uint32_t b0, b1;
                asm volatile("ldmatrix.sync.aligned.m8n8.x2.shared.b16 "
                    "{%0,%1}, [%2];" : "=r"(b0),"=r"(b1) : "r"(bA + kk*32));
                float* dj = d[kk & 3];
                asm volatile(
                    "mma.sync.aligned.m16n8k16.row.col.f32.bf16.bf16.f32 "
                    "{%0,%1,%2,%3}, {%4,%5,%6,%7}, {%8,%9}, {%0,%1,%2,%3};"
                    : "+f"(dj[0]),"+f"(dj[1]),"+f"(dj[2]),"+f"(dj[3])
                    : "r"(afr[kk][0]),"r"(afr[kk][1]),"r"(afr[kk][2]),"r"(afr[kk][3]),
                      "r"(b0),"r"(b1));
            }
        }
        gs[grow0*9     + gcol0]     = (d[0][0]+d[1][0]) + (d[2][0]+d[3][0]);
        gs[grow0*9     + gcol0 + 1] = (d[0][1]+d[1][1]) + (d[2][1]+d[3][1]);
        gs[(grow0+8)*9 + gcol0]     = (d[0][2]+d[1][2]) + (d[2][2]+d[3][2]);
        gs[(grow0+8)*9 + gcol0 + 1] = (d[0][3]+d[1][3]) + (d[2][3]+d[3][3]);
        __syncthreads();

        // elementwise (tanh.approx activations; c stays in register)
        float gi = gs[uu*9      + bb] + xgi;
        float gf = gs[(32+uu)*9 + bb] + xgf;
        float gg = gs[(64+uu)*9 + bb] + xgg;
        float go = gs[(96+uu)*9 + bb] + xgo;
        c_reg = sigm_a(gf)*c_reg + sigm_a(gi)*tanh_a(gg);
        float hh = sigm_a(go)*tanh_a(c_reg);

        if (step + 1 < Tn){
            *reinterpret_cast<__nv_bfloat16*>(sm + OFF_S + bb*64 + uu*2)
                = __float2bfloat16_rn(hh);
            __syncthreads();

            // distribute my 32-unit h slice to all 8 CTAs' next-phase buffer
            {
                int rr = tid >> 5;
                int j  = tid & 31;
                int sb2 = j >> 2;
                int gq  = j & 3;
                u64 v0 = *reinterpret_cast<const u64*>(sm + OFF_S + sb2*64 + gq*16);
                u64 v1 = *reinterpret_cast<const u64*>(sm + OFF_S + sb2*64 + gq*16 + 8);
                uint32_t la = smb + OFF_H + (uint32_t)q*HPH
                            + sb2*(HSTR*2) + (u0<<1) + (gq<<4);
                uint32_t ra;
                asm volatile("mapa.shared::cluster.u32 %0, %1, %2;"
                             : "=r"(ra) : "r"(la), "r"(rr));
                asm volatile("st.shared::cluster.b64 [%0], %1;" :: "r"(ra),   "l"(v0));
                asm volatile("st.shared::cluster.b64 [%0], %1;" :: "r"(ra+8), "l"(v1));
            }
            __syncthreads();     // all pushes issued before the CTA-representative arrives

            // arrive (release, cluster) on every rank's mb[q]
            if (tid < 8){
                uint32_t la = smb + OFF_MB + (uint32_t)q*8;
                uint32_t ra;
                asm volatile("mapa.shared::cluster.u32 %0, %1, %2;"
                             : "=r"(ra) : "r"(la), "r"(tid));
                asm volatile("mbarrier.arrive.release.cluster.shared::cluster.b64 _, [%0];"
                             :: "r"(ra) : "memory");
            }

            // global h store overlaps the wait
            if (layer == 0){
                g_xh[((size_t)bglob*Tn + t)*HIDn + dir*Hn + u0 + uu]
                    = __float2bfloat16_rn(hh);
            } else {
                g_xA[((size_t)bglob*Tn + t)*HIDn + dir*Hn + u0 + uu] = hh;
            }

            // wait (acquire, cluster) on local mb[q]
            {
                uint32_t mba = smb + OFF_MB + (uint32_t)q*8;
                uint32_t parity = q ? ph1 : ph0;
                asm volatile(
                    "{\n\t.reg .pred P;\n\t"
                    "LW%=:\n\t"
                    "mbarrier.try_wait.parity.acquire.cluster.shared::cta.b64 P, [%0], %1, 0x989680;\n\t"
                    "@P bra LD%=;\n\t"
                    "bra LW%=;\n\t"
                    "LD%=:\n\t}"
                    :: "r"(mba), "r"(parity) : "memory");
                if (q) ph1 ^= 1; else ph0 ^= 1;
            }
        } else {
            // final step: no successor, just the global store
            if (layer == 0){
                g_xh[((size_t)bglob*Tn + t)*HIDn + dir*Hn + u0 + uu]
                    = __float2bfloat16_rn(hh);
            } else {
                g_xA[((size_t)bglob*Tn + t)*HIDn + dir*Hn + u0 + uu] = hh;
            }
        }

        xgi = ngi; xgf = ngf; xgg = ngg; xgo = ngo;
    }
}

// ---------------------------------------------------------------------------
// Logits: logits[bt][l] = x[bt][:] . cls_w[l][:] + cls_b[l]   (warp per row)
// ---------------------------------------------------------------------------
__global__ __launch_bounds__(256)
void logits_kernel(const float* __restrict__ cls_w, const float* __restrict__ cls_b){
    int row  = (blockIdx.x << 3) + (threadIdx.x >> 5);
    int lane = threadIdx.x & 31;
    const float* xr = g_xA + (size_t)row*HIDn + lane*16;
    float xv[16];
    #pragma unroll
    for (int q=0;q<4;q++){
        float4 v = *reinterpret_cast<const float4*>(xr + q*4);
        xv[q*4+0]=v.x; xv[q*4+1]=v.y; xv[q*4+2]=v.z; xv[q*4+3]=v.w;
    }
    float myout = 0.f;
    #pragma unroll
    for (int l=0;l<NLn;l++){
        const float* wr = cls_w + l*HIDn + lane*16;
        float p = 0.f;
        #pragma unroll
        for (int j=0;j<16;j++) p = fmaf(xv[j], __ldg(wr+j), p);
        #pragma unroll
        for (int o=16;o;o>>=1) p += __shfl_xor_sync(0xffffffffu, p, o);
        if (lane == l) myout = p + cls_b[l];
    }
    if (lane < NLn) g_logits[(size_t)row*NLn + lane] = myout;
}

// ---------------------------------------------------------------------------
// CRF: one warp per batch element. lanes 0..8 hold states.
// ---------------------------------------------------------------------------
__global__ void crf_kernel(const int* __restrict__ labels,
                           const float* __restrict__ start_trans,
                           const float* __restrict__ end_trans,
                           const float* __restrict__ trans){
    int b    = blockIdx.x;
    int lane = threadIdx.x;
    __shared__ float tr_s[NLn*NLn];
    for (int i = lane; i < NLn*NLn; i += 32) tr_s[i] = trans[i];
    __syncwarp();

    bool act = lane < NLn;
    float tr[NLn];
    #pragma unroll
    for (int k=0;k<NLn;k++) tr[k] = act ? trans[k*NLn + lane] : 0.f;

    const float* lg = g_logits + (size_t)b*Tn*NLn;
    const int*   lb = labels   + (size_t)b*Tn;

    float em    = act ? lg[lane] : -1e30f;
    float alpha = act ? (start_trans[lane] + em) : -1e30f;
    int prev = lb[0];
    float num = __shfl_sync(0xffffffffu, em, prev) + start_trans[prev];

    for (int t=1;t<Tn;t++){
        em = act ? lg[t*NLn + lane] : -1e30f;
        int tag = lb[t];
        float v[NLn], m = -1e30f;
        #pragma unroll
        for (int k=0;k<NLn;k++){
            float ak = __shfl_sync(0xffffffffu, alpha, k);
            v[k] = ak + tr[k];
            m = fmaxf(m, v[k]);
        }
        float s = 0.f;
        #pragma unroll
        for (int k=0;k<NLn;k++) s += __expf(v[k]-m);
        float na = m + __logf(s) + em;
        num += tr_s[prev*NLn + tag] + __shfl_sync(0xffffffffu, em, tag);
        alpha = act ? na : -1e30f;
        prev = tag;
    }
    float fa = act ? (alpha + end_trans[lane]) : -1e30f;
    float m = fa;
    #pragma unroll
    for (int o=16;o;o>>=1) m = fmaxf(m, __shfl_xor_sync(0xffffffffu, m, o));
    float s = act ? __expf(fa - m) : 0.f;
    #pragma unroll
    for (int o=16;o;o>>=1) s += __shfl_xor_sync(0xffffffffu, s, o);
    float denom = m + __logf(s);
    num += end_trans[prev];
    if (lane == 0) g_crf[b] = num - denom;
}

__global__ void finish_kernel(float* out){
    int lane = threadIdx.x;
    float s = g_crf[lane] + g_crf[lane+32];
    #pragma unroll
    for (int o=16;o;o>>=1) s += __shfl_xor_sync(0xffffffffu, s, o);
    if (lane == 0) out[0] = -s;
}

// ---------------------------------------------------------------------------
extern "C" void kernel_launch(void* const* d_in, const int* in_sizes, int n_in,
                              void* d_out, int out_size){
    const int*   ids         = (const int*)  d_in[0];
    const int*   labels      = (const int*)  d_in[1];
    const float* emb         = (const float*)d_in[2];
    const float* w_ih        = (const float*)d_in[3];
    const float* w_hh        = (const float*)d_in[4];
    const float* b_ih        = (const float*)d_in[5];
    const float* b_hh        = (const float*)d_in[6];
    const float* cls_w       = (const float*)d_in[7];
    const float* cls_b       = (const float*)d_in[8];
    const float* start_trans = (const float*)d_in[9];
    const float* end_trans   = (const float*)d_in[10];
    const float* trans       = (const float*)d_in[11];
    float* out = (float*)d_out;

    cudaFuncSetAttribute(lstm_cluster_kernel,
                         cudaFuncAttributeMaxDynamicSharedMemorySize, LSTM_SMEM);
    cudaFuncSetAttribute(gemm_xp_mma,
                         cudaFuncAttributeMaxDynamicSharedMemorySize, GSM_TOTAL);

    embed_kernel<<<BTn,128>>>(ids, emb);

    for (int layer = 0; layer < 2; ++layer){
        conv_w_kernel<<<(2048*HIDn)/2048, 256>>>(w_ih + (size_t)layer*2048*HIDn);
        gemm_xp_mma<<<dim3(16,256),256,GSM_TOTAL>>>(
            b_ih + (size_t)layer*2048,
            b_hh + (size_t)layer*2048);
        lstm_cluster_kernel<<<128,256,LSTM_SMEM>>>(layer,
            w_hh + (size_t)layer*2*G4n*Hn);
    }

    logits_kernel<<<BTn/8,256>>>(cls_w, cls_b);
    crf_kernel<<<Bn,32>>>(labels, start_trans, end_trans, trans);
    finish_kernel<<<1,32>>>(out);
}